// round 7
// baseline (speedup 1.0000x reference)
#include <cuda_runtime.h>
#include <cuda_fp16.h>
#include <cstdint>

#define HDIM  2048
#define MROWS 16384
#define BM    128
#define BN    256
#define BK    64
#define NSPLIT 4
#define NRED  2048

#define A_TILE      (BM * 128)             // 16KB
#define B_TILE      (BN * 128)             // 32KB
#define STAGE       (2 * A_TILE + B_TILE)  // 64KB: Ahi Alo Bhi
#define SMEM_DYN    (3 * STAGE + 1024)     // 3-stage pipeline

// ---------------- device scratch (no allocs allowed) ----------------
__device__ __half g_xhi [(size_t)MROWS * HDIM];
__device__ __half g_xlo [(size_t)MROWS * HDIM];
__device__ __half g_xthi[(size_t)MROWS * HDIM];   // x^T [H, M]
__device__ __half g_xtlo[(size_t)MROWS * HDIM];
__device__ __half g_whi [(size_t)HDIM * HDIM];    // fp16(fw+pw)
__device__ __half g_cthi[(size_t)MROWS * HDIM];   // combined^T [H, M] (hi only)
__device__ float  g_part[(size_t)NSPLIT * HDIM * HDIM];  // split-K partials
__device__ double g_partials[NRED];
__device__ float  g_scale;

// ---------------- PTX helpers (baseline sm_80+ features only) ----------------
__device__ __forceinline__ uint32_t smem_u32(const void* p) {
    uint32_t a;
    asm("{ .reg .u64 t; cvta.to.shared.u64 t, %1; cvt.u32.u64 %0, t; }" : "=r"(a) : "l"(p));
    return a;
}
__device__ __forceinline__ uint32_t sw128(uint32_t o) { return o ^ ((o >> 3) & 0x70); }

__device__ __forceinline__ void cpasync16(uint32_t d, const void* s) {
    asm volatile("cp.async.cg.shared.global [%0], [%1], 16;" :: "r"(d), "l"(s));
}
#define CP_COMMIT() asm volatile("cp.async.commit_group;" ::: "memory")
#define CP_WAIT2()  asm volatile("cp.async.wait_group 2;" ::: "memory")
#define CP_WAIT1()  asm volatile("cp.async.wait_group 1;" ::: "memory")
#define CP_WAIT0()  asm volatile("cp.async.wait_group 0;" ::: "memory")

__device__ __forceinline__ void ldsm4(uint32_t* r, uint32_t addr) {
    asm volatile("ldmatrix.sync.aligned.m8n8.x4.shared.b16 {%0,%1,%2,%3}, [%4];"
                 : "=r"(r[0]), "=r"(r[1]), "=r"(r[2]), "=r"(r[3]) : "r"(addr));
}
__device__ __forceinline__ void mma16816(float* c, const uint32_t* a, const uint32_t* b) {
    asm volatile(
        "mma.sync.aligned.m16n8k16.row.col.f32.f16.f16.f32 "
        "{%0,%1,%2,%3}, {%4,%5,%6,%7}, {%8,%9}, {%0,%1,%2,%3};"
        : "+f"(c[0]), "+f"(c[1]), "+f"(c[2]), "+f"(c[3])
        : "r"(a[0]), "r"(a[1]), "r"(a[2]), "r"(a[3]), "r"(b[0]), "r"(b[1]));
}

// ---------------- split helpers ----------------
__device__ __forceinline__ void split1(float v, __half& h, __half& l) {
    h = __float2half(v);
    l = __float2half(v - __half2float(h));
}

// Fused: read x [R,C] once per 32x32 tile; emit row-major split (xhi/xlo)
// and transposed split (xthi/xtlo [C,R]).
__global__ void xprep_kernel(const float* __restrict__ in,
                             __half* __restrict__ rh, __half* __restrict__ rl,
                             __half* __restrict__ th, __half* __restrict__ tl,
                             int R, int C) {
    __shared__ float t[32][33];
    int tid = threadIdx.x;                 // 256
    int r0 = blockIdx.y * 32, c0 = blockIdx.x * 32;
    int row = tid >> 3, seg = tid & 7;
    float4 v = *(const float4*)(in + (size_t)(r0 + row) * C + c0 + seg * 4);
    // row-major split output (coalesced along C)
    {
        __half h0, h1, h2, h3, l0, l1, l2, l3;
        split1(v.x, h0, l0); split1(v.y, h1, l1); split1(v.z, h2, l2); split1(v.w, h3, l3);
        size_t ob = ((size_t)(r0 + row) * C + c0 + seg * 4) >> 1;
        __half2* ph = (__half2*)rh + ob;
        __half2* pl = (__half2*)rl + ob;
        ph[0] = __halves2half2(h0, h1); ph[1] = __halves2half2(h2, h3);
        pl[0] = __halves2half2(l0, l1); pl[1] = __halves2half2(l2, l3);
    }
    t[row][seg * 4 + 0] = v.x; t[row][seg * 4 + 1] = v.y;
    t[row][seg * 4 + 2] = v.z; t[row][seg * 4 + 3] = v.w;
    __syncthreads();
    int oc = row;
    int rs = seg * 4;
    float a0 = t[rs + 0][oc], a1 = t[rs + 1][oc], a2 = t[rs + 2][oc], a3 = t[rs + 3][oc];
    __half h0, h1, h2, h3, l0, l1, l2, l3;
    split1(a0, h0, l0); split1(a1, h1, l1); split1(a2, h2, l2); split1(a3, h3, l3);
    size_t ob = ((size_t)(c0 + oc) * R + r0 + rs) >> 1;
    __half2* ph = (__half2*)th + ob;
    __half2* pl = (__half2*)tl + ob;
    ph[0] = __halves2half2(h0, h1); ph[1] = __halves2half2(h2, h3);
    pl[0] = __halves2half2(l0, l1); pl[1] = __halves2half2(l2, l3);
}

__global__ void wsum_hi_kernel(const float* __restrict__ fw, const float* __restrict__ pw,
                               __half* __restrict__ oh) {
    size_t i = (size_t)blockIdx.x * blockDim.x + threadIdx.x;
    float4 a = ((const float4*)fw)[i];
    float4 b = ((const float4*)pw)[i];
    __half2* ph = (__half2*)oh + i * 2;
    ph[0] = __halves2half2(__float2half(a.x + b.x), __float2half(a.y + b.y));
    ph[1] = __halves2half2(__float2half(a.z + b.z), __float2half(a.w + b.w));
}

// transpose, hi only: in [R,C] fp32 -> out [C,R] fp16
__global__ void tsplit_hi_kernel(const float* __restrict__ in,
                                 __half* __restrict__ oh, int R, int C) {
    __shared__ float t[32][33];
    int tid = threadIdx.x;
    int r0 = blockIdx.y * 32, c0 = blockIdx.x * 32;
    int row = tid >> 3, seg = tid & 7;
    float4 v = *(const float4*)(in + (size_t)(r0 + row) * C + c0 + seg * 4);
    t[row][seg * 4 + 0] = v.x; t[row][seg * 4 + 1] = v.y;
    t[row][seg * 4 + 2] = v.z; t[row][seg * 4 + 3] = v.w;
    __syncthreads();
    int oc = row;
    int rs = seg * 4;
    __half h0 = __float2half(t[rs + 0][oc]);
    __half h1 = __float2half(t[rs + 1][oc]);
    __half h2 = __float2half(t[rs + 2][oc]);
    __half h3 = __float2half(t[rs + 3][oc]);
    size_t ob = ((size_t)(c0 + oc) * R + r0 + rs) >> 1;
    __half2* ph = (__half2*)oh + ob;
    ph[0] = __halves2half2(h0, h1); ph[1] = __halves2half2(h2, h3);
}

// ---------------- HMMA mainloop: fp16 2-product, warp tile 64x64 ------------
// D[m,n] = sum_k (Ahi+Alo)[m,k] * Bhi[n,k]   (stage = Ahi Alo Bhi)
__device__ __forceinline__ void mm_loop(float acc[4][8][4],
    const __half* __restrict__ Ahi, const __half* __restrict__ Alo,
    const __half* __restrict__ Bhi,
    int lda, int ldb, int m0, int n0, int kbeg, int NC)
{
    constexpr uint32_t A_HI = 0;
    constexpr uint32_t A_LO = A_TILE;
    constexpr uint32_t B_HI = 2 * A_TILE;

    extern __shared__ char dsm[];
    uint32_t raw = smem_u32(dsm);
    uint32_t sbase = (raw + 1023) & ~1023u;

    const int tid  = threadIdx.x;
    const int lane = tid & 31;
    const int wid  = tid >> 5;
    const int wm = (wid >> 2) * 64;        // 2 warp-rows x 64
    const int wn = (wid & 3) * 64;         // 4 warp-cols x 64

    const int arow  = wm + (lane & 15);
    const int akadd = (lane >> 4) << 3;
    const int nrow  = wn + (lane & 7) + ((lane >> 4) << 3);
    const int bkadd = ((lane >> 3) & 1) << 3;

    auto issue = [&](int c) {
        uint32_t sb = sbase + (uint32_t)(c % 3) * STAGE;
        const int k0 = kbeg + c * BK;
        // A tiles: 1024 float4 each
        #pragma unroll
        for (int t = 0; t < 4; t++) {
            int seg = tid + t * 256;
            int r = seg >> 3, sc = seg & 7;
            uint32_t so = sw128((uint32_t)(r * 128 + sc * 16));
            size_t ga = (size_t)(m0 + r) * lda + k0 + sc * 8;
            cpasync16(sb + A_HI + so, Ahi + ga);
            cpasync16(sb + A_LO + so, Alo + ga);
        }
        // B tile: 2048 float4
        #pragma unroll
        for (int t = 0; t < 8; t++) {
            int seg = tid + t * 256;
            int r = seg >> 3, sc = seg & 7;
            uint32_t so = sw128((uint32_t)(r * 128 + sc * 16));
            size_t gb = (size_t)(n0 + r) * ldb + k0 + sc * 8;
            cpasync16(sb + B_HI + so, Bhi + gb);
        }
    };

    issue(0); CP_COMMIT();
    issue(1); CP_COMMIT();

    #pragma unroll 1
    for (int c = 0; c < NC; c++) {
        if (c + 2 < NC) { issue(c + 2); CP_COMMIT(); CP_WAIT2(); }
        else if (c + 1 < NC) { CP_WAIT1(); }
        else { CP_WAIT0(); }
        __syncthreads();

        uint32_t st = sbase + (uint32_t)(c % 3) * STAGE;
        #pragma unroll
        for (int ks = 0; ks < 4; ks++) {
            uint32_t bh[8][2];
            #pragma unroll
            for (int ng = 0; ng < 4; ng++) {
                uint32_t off = sw128((uint32_t)((nrow + ng * 16) * 128 + (ks * 16 + bkadd) * 2));
                uint32_t q[4];
                ldsm4(q, st + B_HI + off);
                bh[2*ng][0] = q[0]; bh[2*ng][1] = q[1];
                bh[2*ng+1][0] = q[2]; bh[2*ng+1][1] = q[3];
            }
            #pragma unroll
            for (int mi = 0; mi < 4; mi++) {
                uint32_t ah[4], al[4];
                uint32_t off = sw128((uint32_t)((arow + mi * 16) * 128 + (ks * 16 + akadd) * 2));
                ldsm4(ah, st + A_HI + off);
                ldsm4(al, st + A_LO + off);
                #pragma unroll
                for (int ni = 0; ni < 8; ni++) {
                    mma16816(acc[mi][ni], ah, bh[ni]);
                    mma16816(acc[mi][ni], al, bh[ni]);
                }
            }
        }
        __syncthreads();
    }
}

// ---------------- GEMM1: combined = x @ Wsum^T + bias ----------------
__global__ __launch_bounds__(256, 1)
void gemm1_mma(const float* __restrict__ bias, float* __restrict__ Cout) {
    float acc[4][8][4];
    #pragma unroll
    for (int i = 0; i < 4; i++)
        #pragma unroll
        for (int j = 0; j < 8; j++)
            #pragma unroll
            for (int q = 0; q < 4; q++) acc[i][j][q] = 0.f;

    const int m0 = blockIdx.y * BM, n0 = blockIdx.x * BN;
    mm_loop(acc, g_xhi, g_xlo, g_whi, HDIM, HDIM, m0, n0, 0, HDIM / BK);

    const int lane = threadIdx.x & 31, wid = threadIdx.x >> 5;
    const int wm = (wid >> 2) * 64, wn = (wid & 3) * 64;
    const int rbase = m0 + wm + (lane >> 2);
    const int cbase = n0 + wn + (lane & 3) * 2;
    #pragma unroll
    for (int mi = 0; mi < 4; mi++)
        #pragma unroll
        for (int ni = 0; ni < 8; ni++) {
            int r = rbase + mi * 16, cc = cbase + ni * 8;
            float2 bv = *(const float2*)(bias + cc);
            *(float2*)(Cout + (size_t)r * HDIM + cc) =
                make_float2(acc[mi][ni][0] + bv.x, acc[mi][ni][1] + bv.y);
            *(float2*)(Cout + (size_t)(r + 8) * HDIM + cc) =
                make_float2(acc[mi][ni][2] + bv.x, acc[mi][ni][3] + bv.y);
        }
}

// ---------------- GEMM2 partial: P[s] = X^T @ C over k-split s ----------------
__global__ __launch_bounds__(256, 1)
void gemm2_mma(int M) {
    float acc[4][8][4];
    #pragma unroll
    for (int i = 0; i < 4; i++)
        #pragma unroll
        for (int j = 0; j < 8; j++)
            #pragma unroll
            for (int q = 0; q < 4; q++) acc[i][j][q] = 0.f;

    const int s = blockIdx.z;
    const int kper = M / NSPLIT;
    const int h0 = blockIdx.y * BM, n0 = blockIdx.x * BN;
    mm_loop(acc, g_xthi, g_xtlo, g_cthi, M, M, h0, n0, s * kper, kper / BK);

    float* P = g_part + (size_t)s * HDIM * HDIM;
    const int lane = threadIdx.x & 31, wid = threadIdx.x >> 5;
    const int wm = (wid >> 2) * 64, wn = (wid & 3) * 64;
    const int rbase = h0 + wm + (lane >> 2);
    const int cbase = n0 + wn + (lane & 3) * 2;
    #pragma unroll
    for (int mi = 0; mi < 4; mi++)
        #pragma unroll
        for (int ni = 0; ni < 8; ni++) {
            int r = rbase + mi * 16, cc = cbase + ni * 8;
            *(float2*)(P + (size_t)r * HDIM + cc) =
                make_float2(acc[mi][ni][0], acc[mi][ni][1]);
            *(float2*)(P + (size_t)(r + 8) * HDIM + cc) =
                make_float2(acc[mi][ni][2], acc[mi][ni][3]);
        }
}

// ---------------- combine + norm + scale ----------------
__global__ void combine_kernel(const float* __restrict__ plastic,
                               const float* __restrict__ rate,
                               const float* __restrict__ hs,
                               float* __restrict__ Wout, float invM) {
    size_t i = (size_t)blockIdx.x * blockDim.x + threadIdx.x;   // float4 index
    const float factor = rate[0] * hs[0] * invM;
    const size_t stride4 = (size_t)HDIM * HDIM / 4;
    float4 s0 = ((const float4*)g_part)[i];
    float4 s1 = ((const float4*)g_part)[i + stride4];
    float4 s2 = ((const float4*)g_part)[i + 2 * stride4];
    float4 s3 = ((const float4*)g_part)[i + 3 * stride4];
    float4 p  = ((const float4*)plastic)[i];
    float4 o;
    o.x = p.x + factor * (s0.x + s1.x + s2.x + s3.x);
    o.y = p.y + factor * (s0.y + s1.y + s2.y + s3.y);
    o.z = p.z + factor * (s0.z + s1.z + s2.z + s3.z);
    o.w = p.w + factor * (s0.w + s1.w + s2.w + s3.w);
    ((float4*)Wout)[i] = o;
}

__global__ void sumsq_kernel(const float* __restrict__ W) {
    __shared__ double sh[256];
    const int tid = threadIdx.x;
    const float4* W4 = (const float4*)W;
    const size_t total4 = (size_t)HDIM * HDIM / 4;
    double s = 0.0;
    for (size_t i = (size_t)blockIdx.x * 256 + tid; i < total4;
         i += (size_t)gridDim.x * 256) {
        float4 v = W4[i];
        s += (double)v.x * v.x + (double)v.y * v.y
           + (double)v.z * v.z + (double)v.w * v.w;
    }
    sh[tid] = s;
    __syncthreads();
    for (int off = 128; off > 0; off >>= 1) {
        if (tid < off) sh[tid] += sh[tid + off];
        __syncthreads();
    }
    if (tid == 0) g_partials[blockIdx.x] = sh[0];
}

__global__ void finalize_kernel() {
    __shared__ double sh[256];
    const int tid = threadIdx.x;
    double s = 0.0;
    for (int i = tid; i < NRED; i += 256) s += g_partials[i];
    sh[tid] = s;
    __syncthreads();
    for (int off = 128; off > 0; off >>= 1) {
        if (tid < off) sh[tid] += sh[tid + off];
        __syncthreads();
    }
    if (tid == 0) {
        double norm = sqrt(sh[0]);
        g_scale = (norm > 1.0) ? (float)(1.0 / norm) : 1.0f;
    }
}

__global__ void scale_kernel(float* __restrict__ W) {
    size_t i = (size_t)blockIdx.x * blockDim.x + threadIdx.x;
    const float s = g_scale;
    float4 v = ((float4*)W)[i];
    v.x *= s; v.y *= s; v.z *= s; v.w *= s;
    ((float4*)W)[i] = v;
}

// ---------------- launch ----------------
extern "C" void kernel_launch(void* const* d_in, const int* in_sizes, int n_in,
                              void* d_out, int out_size) {
    const float* x    = (const float*)d_in[0];  // [M, H]
    const float* pw   = (const float*)d_in[1];  // [H, H]
    const float* rate = (const float*)d_in[2];  // [1]
    const float* fw   = (const float*)d_in[3];  // [H, H]
    const float* fb   = (const float*)d_in[4];  // [H]
    const float* hs   = (const float*)d_in[5];  // scalar

    const int M = in_sizes[0] / HDIM;           // 16384
    float* combined = (float*)d_out;
    float* neww     = (float*)d_out + (size_t)M * HDIM;

    static bool attr_done = false;
    if (!attr_done) {
        cudaFuncSetAttribute(gemm1_mma, cudaFuncAttributeMaxDynamicSharedMemorySize, SMEM_DYN);
        cudaFuncSetAttribute(gemm2_mma, cudaFuncAttributeMaxDynamicSharedMemorySize, SMEM_DYN);
        attr_done = true;
    }

    __half *xhi, *xlo, *xthi, *xtlo, *whi, *cthi;
    cudaGetSymbolAddress((void**)&xhi,  g_xhi);
    cudaGetSymbolAddress((void**)&xlo,  g_xlo);
    cudaGetSymbolAddress((void**)&xthi, g_xthi);
    cudaGetSymbolAddress((void**)&xtlo, g_xtlo);
    cudaGetSymbolAddress((void**)&whi,  g_whi);
    cudaGetSymbolAddress((void**)&cthi, g_cthi);

    // operand prep: wsum (hi) + fused x split/transpose-split
    wsum_hi_kernel<<<HDIM * HDIM / 4 / 256, 256>>>(fw, pw, whi);
    {
        dim3 g(HDIM / 32, M / 32);
        xprep_kernel<<<g, 256>>>(x, xhi, xlo, xthi, xtlo, M, HDIM);
    }

    // GEMM1
    {
        dim3 g(HDIM / BN, M / BM);
        gemm1_mma<<<g, 256, SMEM_DYN>>>(fb, combined);
    }

    // transpose combined -> [H, M] (hi only)
    {
        dim3 g(HDIM / 32, M / 32);
        tsplit_hi_kernel<<<g, 256>>>(combined, cthi, M, HDIM);
    }

    // GEMM2 split-K partials, then deterministic combine
    {
        dim3 g(HDIM / BN, HDIM / BM, NSPLIT);
        gemm2_mma<<<g, 256, SMEM_DYN>>>(M);
    }
    combine_kernel<<<HDIM * HDIM / 4 / 256, 256>>>(pw, rate, hs, neww, 1.0f / (float)M);

    sumsq_kernel<<<NRED, 256>>>(neww);
    finalize_kernel<<<1, 256>>>();
    scale_kernel<<<HDIM * HDIM / 4 / 256, 256>>>(neww);
}

// round 8
// speedup vs baseline: 1.5127x; 1.5127x over previous
#include <cuda_runtime.h>
#include <cuda_fp16.h>
#include <cstdint>

#define HDIM  2048
#define MROWS 16384
#define BM    128
#define BN    128
#define BK    64
#define NSPLIT 4
#define NRED  2048

#define TILE_BYTES  (128 * 128)        // 16KB: 128 rows x 128B (64 fp16)
#define STAGE3      (3 * TILE_BYTES)   // stage: Ahi Alo Bhi (48KB)
#define SMEM_DYN    (3 * STAGE3 + 1024)

// ---------------- device scratch (no allocs allowed) ----------------
__device__ __half g_xhi [(size_t)MROWS * HDIM];
__device__ __half g_xlo [(size_t)MROWS * HDIM];
__device__ __half g_xthi[(size_t)MROWS * HDIM];   // x^T [H, M]
__device__ __half g_xtlo[(size_t)MROWS * HDIM];
__device__ __half g_whi [(size_t)HDIM * HDIM];    // fp16(fw+pw)
__device__ __half g_cthi[(size_t)MROWS * HDIM];   // combined^T [H, M] (hi only)
__device__ float  g_part[(size_t)NSPLIT * HDIM * HDIM];  // split-K partials
__device__ double g_partials[NRED];
__device__ float  g_scale;

// ---------------- PTX helpers (baseline sm_80+ features only) ----------------
__device__ __forceinline__ uint32_t smem_u32(const void* p) {
    uint32_t a;
    asm("{ .reg .u64 t; cvta.to.shared.u64 t, %1; cvt.u32.u64 %0, t; }" : "=r"(a) : "l"(p));
    return a;
}
__device__ __forceinline__ uint32_t sw128(uint32_t o) { return o ^ ((o >> 3) & 0x70); }

__device__ __forceinline__ void cpasync16(uint32_t d, const void* s) {
    asm volatile("cp.async.cg.shared.global [%0], [%1], 16;" :: "r"(d), "l"(s));
}
#define CP_COMMIT() asm volatile("cp.async.commit_group;" ::: "memory")
#define CP_WAIT2()  asm volatile("cp.async.wait_group 2;" ::: "memory")
#define CP_WAIT1()  asm volatile("cp.async.wait_group 1;" ::: "memory")
#define CP_WAIT0()  asm volatile("cp.async.wait_group 0;" ::: "memory")

__device__ __forceinline__ void ldsm4(uint32_t* r, uint32_t addr) {
    asm volatile("ldmatrix.sync.aligned.m8n8.x4.shared.b16 {%0,%1,%2,%3}, [%4];"
                 : "=r"(r[0]), "=r"(r[1]), "=r"(r[2]), "=r"(r[3]) : "r"(addr));
}
__device__ __forceinline__ void mma16816(float* c, const uint32_t* a, const uint32_t* b) {
    asm volatile(
        "mma.sync.aligned.m16n8k16.row.col.f32.f16.f16.f32 "
        "{%0,%1,%2,%3}, {%4,%5,%6,%7}, {%8,%9}, {%0,%1,%2,%3};"
        : "+f"(c[0]), "+f"(c[1]), "+f"(c[2]), "+f"(c[3])
        : "r"(a[0]), "r"(a[1]), "r"(a[2]), "r"(a[3]), "r"(b[0]), "r"(b[1]));
}

// ---------------- split helpers ----------------
__device__ __forceinline__ void split1(float v, __half& h, __half& l) {
    h = __float2half(v);
    l = __float2half(v - __half2float(h));
}

// Fused: read x [R,C] once per 32x32 tile; emit row-major split (xhi/xlo)
// and transposed split (xthi/xtlo [C,R]).
__global__ void xprep_kernel(const float* __restrict__ in,
                             __half* __restrict__ rh, __half* __restrict__ rl,
                             __half* __restrict__ th, __half* __restrict__ tl,
                             int R, int C) {
    __shared__ float t[32][33];
    int tid = threadIdx.x;                 // 256
    int r0 = blockIdx.y * 32, c0 = blockIdx.x * 32;
    int row = tid >> 3, seg = tid & 7;
    float4 v = *(const float4*)(in + (size_t)(r0 + row) * C + c0 + seg * 4);
    {
        __half h0, h1, h2, h3, l0, l1, l2, l3;
        split1(v.x, h0, l0); split1(v.y, h1, l1); split1(v.z, h2, l2); split1(v.w, h3, l3);
        size_t ob = ((size_t)(r0 + row) * C + c0 + seg * 4) >> 1;
        __half2* ph = (__half2*)rh + ob;
        __half2* pl = (__half2*)rl + ob;
        ph[0] = __halves2half2(h0, h1); ph[1] = __halves2half2(h2, h3);
        pl[0] = __halves2half2(l0, l1); pl[1] = __halves2half2(l2, l3);
    }
    t[row][seg * 4 + 0] = v.x; t[row][seg * 4 + 1] = v.y;
    t[row][seg * 4 + 2] = v.z; t[row][seg * 4 + 3] = v.w;
    __syncthreads();
    int oc = row;
    int rs = seg * 4;
    float a0 = t[rs + 0][oc], a1 = t[rs + 1][oc], a2 = t[rs + 2][oc], a3 = t[rs + 3][oc];
    __half h0, h1, h2, h3, l0, l1, l2, l3;
    split1(a0, h0, l0); split1(a1, h1, l1); split1(a2, h2, l2); split1(a3, h3, l3);
    size_t ob = ((size_t)(c0 + oc) * R + r0 + rs) >> 1;
    __half2* ph = (__half2*)th + ob;
    __half2* pl = (__half2*)tl + ob;
    ph[0] = __halves2half2(h0, h1); ph[1] = __halves2half2(h2, h3);
    pl[0] = __halves2half2(l0, l1); pl[1] = __halves2half2(l2, l3);
}

__global__ void wsum_hi_kernel(const float* __restrict__ fw, const float* __restrict__ pw,
                               __half* __restrict__ oh) {
    size_t i = (size_t)blockIdx.x * blockDim.x + threadIdx.x;
    float4 a = ((const float4*)fw)[i];
    float4 b = ((const float4*)pw)[i];
    __half2* ph = (__half2*)oh + i * 2;
    ph[0] = __halves2half2(__float2half(a.x + b.x), __float2half(a.y + b.y));
    ph[1] = __halves2half2(__float2half(a.z + b.z), __float2half(a.w + b.w));
}

// ---------------- HMMA mainloop: fp16 2-product split, 3-stage pipeline -----
// D[m,n] = sum_k (Ahi+Alo)[m,k] * Bhi[n,k]   (stage = Ahi Alo Bhi)
__device__ __forceinline__ void mm_loop(float acc[4][4][4],
    const __half* __restrict__ Ahi, const __half* __restrict__ Alo,
    const __half* __restrict__ Bhi,
    int lda, int ldb, int m0, int n0, int kbeg, int NC)
{
    constexpr uint32_t A_HI = 0;
    constexpr uint32_t A_LO = TILE_BYTES;
    constexpr uint32_t B_HI = 2 * TILE_BYTES;

    extern __shared__ char dsm[];
    uint32_t raw = smem_u32(dsm);
    uint32_t sbase = (raw + 1023) & ~1023u;

    const int tid  = threadIdx.x;
    const int lane = tid & 31;
    const int wid  = tid >> 5;
    const int wm = (wid >> 2) * 64;
    const int wn = (wid & 3) * 32;

    const int arow  = wm + (lane & 15);
    const int akadd = (lane >> 4) << 3;
    const int nrow  = wn + (lane & 7) + ((lane >> 4) << 3);
    const int bkadd = ((lane >> 3) & 1) << 3;

    auto issue = [&](int c) {
        uint32_t sb = sbase + (uint32_t)(c % 3) * STAGE3;
        const int k0 = kbeg + c * BK;
        #pragma unroll
        for (int t = 0; t < 4; t++) {
            int seg = tid + t * 256;
            int r = seg >> 3, sc = seg & 7;
            uint32_t so = sw128((uint32_t)(r * 128 + sc * 16));
            size_t ga = (size_t)(m0 + r) * lda + k0 + sc * 8;
            size_t gb = (size_t)(n0 + r) * ldb + k0 + sc * 8;
            cpasync16(sb + A_HI + so, Ahi + ga);
            cpasync16(sb + A_LO + so, Alo + ga);
            cpasync16(sb + B_HI + so, Bhi + gb);
        }
    };

    issue(0); CP_COMMIT();
    issue(1); CP_COMMIT();

    #pragma unroll 1
    for (int c = 0; c < NC; c++) {
        if (c + 2 < NC) { issue(c + 2); CP_COMMIT(); CP_WAIT2(); }
        else if (c + 1 < NC) { CP_WAIT1(); }
        else { CP_WAIT0(); }
        __syncthreads();

        uint32_t st = sbase + (uint32_t)(c % 3) * STAGE3;
        #pragma unroll
        for (int ks = 0; ks < 4; ks++) {
            uint32_t ah[4][4], al[4][4], bh[4][2];
            #pragma unroll
            for (int mi = 0; mi < 4; mi++) {
                uint32_t off = sw128((uint32_t)((arow + mi * 16) * 128 + (ks * 16 + akadd) * 2));
                ldsm4(ah[mi], st + A_HI + off);
                ldsm4(al[mi], st + A_LO + off);
            }
            #pragma unroll
            for (int ng = 0; ng < 2; ng++) {
                uint32_t off = sw128((uint32_t)((nrow + ng * 16) * 128 + (ks * 16 + bkadd) * 2));
                uint32_t q[4];
                ldsm4(q, st + B_HI + off);
                bh[2*ng][0] = q[0]; bh[2*ng][1] = q[1];
                bh[2*ng+1][0] = q[2]; bh[2*ng+1][1] = q[3];
            }
            #pragma unroll
            for (int mi = 0; mi < 4; mi++)
                #pragma unroll
                for (int ni = 0; ni < 4; ni++) {
                    mma16816(acc[mi][ni], ah[mi], bh[ni]);
                    mma16816(acc[mi][ni], al[mi], bh[ni]);
                }
        }
        __syncthreads();
    }
}

// ---------------- GEMM1: combined = x @ Wsum^T + bias; also writes
// combined^T (fp16 hi) via per-warp SMEM transpose ----------------
__global__ __launch_bounds__(256, 1)
void gemm1_mma(const float* __restrict__ bias, float* __restrict__ Cout,
               __half* __restrict__ cth, int Mtot) {
    float acc[4][4][4];
    #pragma unroll
    for (int i = 0; i < 4; i++)
        #pragma unroll
        for (int j = 0; j < 4; j++)
            #pragma unroll
            for (int q = 0; q < 4; q++) acc[i][j][q] = 0.f;

    const int m0 = blockIdx.y * BM, n0 = blockIdx.x * BN;
    mm_loop(acc, g_xhi, g_xlo, g_whi, HDIM, HDIM, m0, n0, 0, HDIM / BK);

    extern __shared__ char dsm[];
    uint32_t raw = smem_u32(dsm);
    char* smp = dsm + (((raw + 1023) & ~1023u) - raw);

    const int lane = threadIdx.x & 31, wid = threadIdx.x >> 5;
    const int wm = (wid >> 2) * 64, wn = (wid & 3) * 32;
    const int rl = lane >> 2;          // local row 0..15 base
    const int cl = (lane & 3) * 2;     // local col pair base
    const int rbase = m0 + wm + rl;
    const int cbase = n0 + wn + cl;

    // per-warp transpose buffer: 32 n-rows x 66 halfs (132B stride, u32-conflict-free)
    __half* tb = (__half*)(smp) + (size_t)wid * (32 * 66);

    __syncthreads();   // pipeline smem fully consumed before reuse
    #pragma unroll
    for (int mi = 0; mi < 4; mi++)
        #pragma unroll
        for (int ni = 0; ni < 4; ni++) {
            int r = rbase + mi * 16, cc = cbase + ni * 8;
            float2 bv = *(const float2*)(bias + cc);
            float v0 = acc[mi][ni][0] + bv.x, v1 = acc[mi][ni][1] + bv.y;
            float v2 = acc[mi][ni][2] + bv.x, v3 = acc[mi][ni][3] + bv.y;
            *(float2*)(Cout + (size_t)r * HDIM + cc)       = make_float2(v0, v1);
            *(float2*)(Cout + (size_t)(r + 8) * HDIM + cc) = make_float2(v2, v3);
            int lr = rl + mi * 16;         // local m 0..63
            int lc = cl + ni * 8;          // local n 0..31
            tb[(lc + 0) * 66 + lr]     = __float2half(v0);
            tb[(lc + 1) * 66 + lr]     = __float2half(v1);
            tb[(lc + 0) * 66 + lr + 8] = __float2half(v2);
            tb[(lc + 1) * 66 + lr + 8] = __float2half(v3);
        }
    __syncwarp();
    // each lane streams one n-row (64 halfs) to cthi[n][m0+wm .. +64)
    {
        const uint32_t* src = (const uint32_t*)(tb + lane * 66);
        size_t n = (size_t)(n0 + wn + lane);
        __half* dst = cth + n * Mtot + m0 + wm;
        #pragma unroll
        for (int j = 0; j < 8; j++) {
            uint4 v;
            v.x = src[j * 4 + 0]; v.y = src[j * 4 + 1];
            v.z = src[j * 4 + 2]; v.w = src[j * 4 + 3];
            *(uint4*)(dst + j * 8) = v;
        }
    }
}

// ---------------- GEMM2 partial: P[s] = X^T @ C over k-split s ----------------
__global__ __launch_bounds__(256, 1)
void gemm2_mma(int M) {
    float acc[4][4][4];
    #pragma unroll
    for (int i = 0; i < 4; i++)
        #pragma unroll
        for (int j = 0; j < 4; j++)
            #pragma unroll
            for (int q = 0; q < 4; q++) acc[i][j][q] = 0.f;

    const int s = blockIdx.z;
    const int kper = M / NSPLIT;
    const int h0 = blockIdx.y * BM, n0 = blockIdx.x * BN;
    mm_loop(acc, g_xthi, g_xtlo, g_cthi, M, M, h0, n0, s * kper, kper / BK);

    float* P = g_part + (size_t)s * HDIM * HDIM;
    const int lane = threadIdx.x & 31, wid = threadIdx.x >> 5;
    const int wm = (wid >> 2) * 64, wn = (wid & 3) * 32;
    const int rbase = h0 + wm + (lane >> 2);
    const int cbase = n0 + wn + (lane & 3) * 2;
    #pragma unroll
    for (int mi = 0; mi < 4; mi++)
        #pragma unroll
        for (int ni = 0; ni < 4; ni++) {
            int r = rbase + mi * 16, cc = cbase + ni * 8;
            *(float2*)(P + (size_t)r * HDIM + cc) =
                make_float2(acc[mi][ni][0], acc[mi][ni][1]);
            *(float2*)(P + (size_t)(r + 8) * HDIM + cc) =
                make_float2(acc[mi][ni][2], acc[mi][ni][3]);
        }
}

// ---------------- combine + norm + scale ----------------
__global__ void combine_kernel(const float* __restrict__ plastic,
                               const float* __restrict__ rate,
                               const float* __restrict__ hs,
                               float* __restrict__ Wout, float invM) {
    size_t i = (size_t)blockIdx.x * blockDim.x + threadIdx.x;   // float4 index
    const float factor = rate[0] * hs[0] * invM;
    const size_t stride4 = (size_t)HDIM * HDIM / 4;
    float4 s0 = ((const float4*)g_part)[i];
    float4 s1 = ((const float4*)g_part)[i + stride4];
    float4 s2 = ((const float4*)g_part)[i + 2 * stride4];
    float4 s3 = ((const float4*)g_part)[i + 3 * stride4];
    float4 p  = ((const float4*)plastic)[i];
    float4 o;
    o.x = p.x + factor * (s0.x + s1.x + s2.x + s3.x);
    o.y = p.y + factor * (s0.y + s1.y + s2.y + s3.y);
    o.z = p.z + factor * (s0.z + s1.z + s2.z + s3.z);
    o.w = p.w + factor * (s0.w + s1.w + s2.w + s3.w);
    ((float4*)Wout)[i] = o;
}

__global__ void sumsq_kernel(const float* __restrict__ W) {
    __shared__ double sh[256];
    const int tid = threadIdx.x;
    const float4* W4 = (const float4*)W;
    const size_t total4 = (size_t)HDIM * HDIM / 4;
    double s = 0.0;
    for (size_t i = (size_t)blockIdx.x * 256 + tid; i < total4;
         i += (size_t)gridDim.x * 256) {
        float4 v = W4[i];
        s += (double)v.x * v.x + (double)v.y * v.y
           + (double)v.z * v.z + (double)v.w * v.w;
    }
    sh[tid] = s;
    __syncthreads();
    for (int off = 128; off > 0; off >>= 1) {
        if (tid < off) sh[tid] += sh[tid + off];
        __syncthreads();
    }
    if (tid == 0) g_partials[blockIdx.x] = sh[0];
}

__global__ void finalize_kernel() {
    __shared__ double sh[256];
    const int tid = threadIdx.x;
    double s = 0.0;
    for (int i = tid; i < NRED; i += 256) s += g_partials[i];
    sh[tid] = s;
    __syncthreads();
    for (int off = 128; off > 0; off >>= 1) {
        if (tid < off) sh[tid] += sh[tid + off];
        __syncthreads();
    }
    if (tid == 0) {
        double norm = sqrt(sh[0]);
        g_scale = (norm > 1.0) ? (float)(1.0 / norm) : 1.0f;
    }
}

__global__ void scale_kernel(float* __restrict__ W) {
    size_t i = (size_t)blockIdx.x * blockDim.x + threadIdx.x;
    const float s = g_scale;
    float4 v = ((float4*)W)[i];
    v.x *= s; v.y *= s; v.z *= s; v.w *= s;
    ((float4*)W)[i] = v;
}

// ---------------- launch ----------------
extern "C" void kernel_launch(void* const* d_in, const int* in_sizes, int n_in,
                              void* d_out, int out_size) {
    const float* x    = (const float*)d_in[0];  // [M, H]
    const float* pw   = (const float*)d_in[1];  // [H, H]
    const float* rate = (const float*)d_in[2];  // [1]
    const float* fw   = (const float*)d_in[3];  // [H, H]
    const float* fb   = (const float*)d_in[4];  // [H]
    const float* hs   = (const float*)d_in[5];  // scalar

    const int M = in_sizes[0] / HDIM;           // 16384
    float* combined = (float*)d_out;
    float* neww     = (float*)d_out + (size_t)M * HDIM;

    static bool attr_done = false;
    if (!attr_done) {
        cudaFuncSetAttribute(gemm1_mma, cudaFuncAttributeMaxDynamicSharedMemorySize, SMEM_DYN);
        cudaFuncSetAttribute(gemm2_mma, cudaFuncAttributeMaxDynamicSharedMemorySize, SMEM_DYN);
        attr_done = true;
    }

    __half *xhi, *xlo, *xthi, *xtlo, *whi, *cthi;
    cudaGetSymbolAddress((void**)&xhi,  g_xhi);
    cudaGetSymbolAddress((void**)&xlo,  g_xlo);
    cudaGetSymbolAddress((void**)&xthi, g_xthi);
    cudaGetSymbolAddress((void**)&xtlo, g_xtlo);
    cudaGetSymbolAddress((void**)&whi,  g_whi);
    cudaGetSymbolAddress((void**)&cthi, g_cthi);

    // operand prep: wsum (hi) + fused x split/transpose-split
    wsum_hi_kernel<<<HDIM * HDIM / 4 / 256, 256>>>(fw, pw, whi);
    {
        dim3 g(HDIM / 32, M / 32);
        xprep_kernel<<<g, 256>>>(x, xhi, xlo, xthi, xtlo, M, HDIM);
    }

    // GEMM1 (writes combined fp32 + combined^T fp16-hi)
    {
        dim3 g(HDIM / BN, M / BM);
        gemm1_mma<<<g, 256, SMEM_DYN>>>(fb, combined, cthi, M);
    }

    // GEMM2 split-K partials, then deterministic combine
    {
        dim3 g(HDIM / BN, HDIM / BM, NSPLIT);
        gemm2_mma<<<g, 256, SMEM_DYN>>>(M);
    }
    combine_kernel<<<HDIM * HDIM / 4 / 256, 256>>>(pw, rate, hs, neww, 1.0f / (float)M);

    sumsq_kernel<<<NRED, 256>>>(neww);
    finalize_kernel<<<1, 256>>>();
    scale_kernel<<<HDIM * HDIM / 4 / 256, 256>>>(neww);
}

// round 9
// speedup vs baseline: 1.9746x; 1.3054x over previous
#include <cuda_runtime.h>
#include <cuda_fp16.h>
#include <cstdint>

#define HDIM  2048
#define MROWS 16384
#define BM    128
#define BN    128
#define BK    64
#define NSPLIT 4
#define NRED  2048

#define TILE_BYTES  (128 * 128)          // 16KB: 128 rows x 128B (64 fp16)
#define STAGE_P2    (3 * TILE_BYTES)     // gemm1 stage: Ahi Alo Bhi (48KB)
#define STAGE_P1    (2 * TILE_BYTES)     // gemm2 stage: Ahi Bhi (32KB)
#define SMEM1       (3 * STAGE_P2 + 1024)
#define SMEM2       (3 * STAGE_P1 + 1024)

// ---------------- device scratch (no allocs allowed) ----------------
__device__ __half g_xhi [(size_t)MROWS * HDIM];
__device__ __half g_xlo [(size_t)MROWS * HDIM];
__device__ __half g_xthi[(size_t)MROWS * HDIM];   // x^T [H, M]
__device__ __half g_whi [(size_t)HDIM * HDIM];    // fp16(fw+pw)
__device__ __half g_cthi[(size_t)MROWS * HDIM];   // combined^T [H, M] (hi only)
__device__ float  g_part[(size_t)NSPLIT * HDIM * HDIM];  // split-K partials
__device__ double g_partials[NRED];
__device__ float  g_scale;

// ---------------- PTX helpers (baseline sm_80+ features only) ----------------
__device__ __forceinline__ uint32_t smem_u32(const void* p) {
    uint32_t a;
    asm("{ .reg .u64 t; cvta.to.shared.u64 t, %1; cvt.u32.u64 %0, t; }" : "=r"(a) : "l"(p));
    return a;
}
__device__ __forceinline__ uint32_t sw128(uint32_t o) { return o ^ ((o >> 3) & 0x70); }

__device__ __forceinline__ void cpasync16(uint32_t d, const void* s) {
    asm volatile("cp.async.cg.shared.global [%0], [%1], 16;" :: "r"(d), "l"(s));
}
#define CP_COMMIT() asm volatile("cp.async.commit_group;" ::: "memory")
#define CP_WAIT2()  asm volatile("cp.async.wait_group 2;" ::: "memory")
#define CP_WAIT1()  asm volatile("cp.async.wait_group 1;" ::: "memory")
#define CP_WAIT0()  asm volatile("cp.async.wait_group 0;" ::: "memory")

__device__ __forceinline__ void ldsm4(uint32_t* r, uint32_t addr) {
    asm volatile("ldmatrix.sync.aligned.m8n8.x4.shared.b16 {%0,%1,%2,%3}, [%4];"
                 : "=r"(r[0]), "=r"(r[1]), "=r"(r[2]), "=r"(r[3]) : "r"(addr));
}
__device__ __forceinline__ void mma16816(float* c, const uint32_t* a, const uint32_t* b) {
    asm volatile(
        "mma.sync.aligned.m16n8k16.row.col.f32.f16.f16.f32 "
        "{%0,%1,%2,%3}, {%4,%5,%6,%7}, {%8,%9}, {%0,%1,%2,%3};"
        : "+f"(c[0]), "+f"(c[1]), "+f"(c[2]), "+f"(c[3])
        : "r"(a[0]), "r"(a[1]), "r"(a[2]), "r"(a[3]), "r"(b[0]), "r"(b[1]));
}

// ---------------- split helpers ----------------
__device__ __forceinline__ void split1(float v, __half& h, __half& l) {
    h = __float2half(v);
    l = __float2half(v - __half2float(h));
}

// Fused: read x [R,C] once per 32x32 tile; emit row-major split (xhi/xlo)
// and transposed hi (xthi [C,R]).
__global__ void xprep_kernel(const float* __restrict__ in,
                             __half* __restrict__ rh, __half* __restrict__ rl,
                             __half* __restrict__ th,
                             int R, int C) {
    __shared__ float t[32][33];
    int tid = threadIdx.x;                 // 256
    int r0 = blockIdx.y * 32, c0 = blockIdx.x * 32;
    int row = tid >> 3, seg = tid & 7;
    float4 v = *(const float4*)(in + (size_t)(r0 + row) * C + c0 + seg * 4);
    {
        __half h0, h1, h2, h3, l0, l1, l2, l3;
        split1(v.x, h0, l0); split1(v.y, h1, l1); split1(v.z, h2, l2); split1(v.w, h3, l3);
        size_t ob = ((size_t)(r0 + row) * C + c0 + seg * 4) >> 1;
        __half2* ph = (__half2*)rh + ob;
        __half2* pl = (__half2*)rl + ob;
        ph[0] = __halves2half2(h0, h1); ph[1] = __halves2half2(h2, h3);
        pl[0] = __halves2half2(l0, l1); pl[1] = __halves2half2(l2, l3);
    }
    t[row][seg * 4 + 0] = v.x; t[row][seg * 4 + 1] = v.y;
    t[row][seg * 4 + 2] = v.z; t[row][seg * 4 + 3] = v.w;
    __syncthreads();
    int oc = row;
    int rs = seg * 4;
    __half h0 = __float2half(t[rs + 0][oc]);
    __half h1 = __float2half(t[rs + 1][oc]);
    __half h2 = __float2half(t[rs + 2][oc]);
    __half h3 = __float2half(t[rs + 3][oc]);
    size_t ob = ((size_t)(c0 + oc) * R + r0 + rs) >> 1;
    __half2* ph = (__half2*)th + ob;
    ph[0] = __halves2half2(h0, h1); ph[1] = __halves2half2(h2, h3);
}

__global__ void wsum_hi_kernel(const float* __restrict__ fw, const float* __restrict__ pw,
                               __half* __restrict__ oh) {
    size_t i = (size_t)blockIdx.x * blockDim.x + threadIdx.x;
    float4 a = ((const float4*)fw)[i];
    float4 b = ((const float4*)pw)[i];
    __half2* ph = (__half2*)oh + i * 2;
    ph[0] = __halves2half2(__float2half(a.x + b.x), __float2half(a.y + b.y));
    ph[1] = __halves2half2(__float2half(a.z + b.z), __float2half(a.w + b.w));
}

// ---------------- HMMA mainloop, templated product count ----------------
// NPROD=2: D = (Ahi+Alo) * Bhi   (stage = Ahi Alo Bhi)
// NPROD=1: D = Ahi * Bhi         (stage = Ahi Bhi)
template <int NPROD>
__device__ __forceinline__ void mm_loop(float acc[4][4][4],
    const __half* __restrict__ Ahi, const __half* __restrict__ Alo,
    const __half* __restrict__ Bhi,
    int lda, int ldb, int m0, int n0, int kbeg, int NC)
{
    constexpr uint32_t A_HI = 0;
    constexpr uint32_t A_LO = TILE_BYTES;                       // NPROD==2 only
    constexpr uint32_t B_HI = (NPROD == 2) ? 2u * TILE_BYTES : TILE_BYTES;
    constexpr uint32_t STG  = (NPROD == 2) ? STAGE_P2 : STAGE_P1;

    extern __shared__ char dsm[];
    uint32_t raw = smem_u32(dsm);
    uint32_t sbase = (raw + 1023) & ~1023u;

    const int tid  = threadIdx.x;
    const int lane = tid & 31;
    const int wid  = tid >> 5;
    const int wm = (wid >> 2) * 64;
    const int wn = (wid & 3) * 32;

    const int arow  = wm + (lane & 15);
    const int akadd = (lane >> 4) << 3;
    const int nrow  = wn + (lane & 7) + ((lane >> 4) << 3);
    const int bkadd = ((lane >> 3) & 1) << 3;

    auto issue = [&](int c) {
        uint32_t sb = sbase + (uint32_t)(c % 3) * STG;
        const int k0 = kbeg + c * BK;
        #pragma unroll
        for (int t = 0; t < 4; t++) {
            int seg = tid + t * 256;
            int r = seg >> 3, sc = seg & 7;
            uint32_t so = sw128((uint32_t)(r * 128 + sc * 16));
            size_t ga = (size_t)(m0 + r) * lda + k0 + sc * 8;
            size_t gb = (size_t)(n0 + r) * ldb + k0 + sc * 8;
            cpasync16(sb + A_HI + so, Ahi + ga);
            if (NPROD == 2) cpasync16(sb + A_LO + so, Alo + ga);
            cpasync16(sb + B_HI + so, Bhi + gb);
        }
    };

    issue(0); CP_COMMIT();
    issue(1); CP_COMMIT();

    #pragma unroll 1
    for (int c = 0; c < NC; c++) {
        if (c + 2 < NC) { issue(c + 2); CP_COMMIT(); CP_WAIT2(); }
        else if (c + 1 < NC) { CP_WAIT1(); }
        else { CP_WAIT0(); }
        __syncthreads();

        uint32_t st = sbase + (uint32_t)(c % 3) * STG;
        #pragma unroll
        for (int ks = 0; ks < 4; ks++) {
            uint32_t ah[4][4], al[4][4], bh[4][2];
            #pragma unroll
            for (int mi = 0; mi < 4; mi++) {
                uint32_t off = sw128((uint32_t)((arow + mi * 16) * 128 + (ks * 16 + akadd) * 2));
                ldsm4(ah[mi], st + A_HI + off);
                if (NPROD == 2) ldsm4(al[mi], st + A_LO + off);
            }
            #pragma unroll
            for (int ng = 0; ng < 2; ng++) {
                uint32_t off = sw128((uint32_t)((nrow + ng * 16) * 128 + (ks * 16 + bkadd) * 2));
                uint32_t q[4];
                ldsm4(q, st + B_HI + off);
                bh[2*ng][0] = q[0]; bh[2*ng][1] = q[1];
                bh[2*ng+1][0] = q[2]; bh[2*ng+1][1] = q[3];
            }
            #pragma unroll
            for (int mi = 0; mi < 4; mi++)
                #pragma unroll
                for (int ni = 0; ni < 4; ni++) {
                    mma16816(acc[mi][ni], ah[mi], bh[ni]);
                    if (NPROD == 2) mma16816(acc[mi][ni], al[mi], bh[ni]);
                }
        }
        __syncthreads();
    }
}

// ---------------- GEMM1: combined = x @ Wsum^T + bias; also writes
// combined^T (fp16 hi) via per-warp SMEM transpose ----------------
__global__ __launch_bounds__(256, 1)
void gemm1_mma(const float* __restrict__ bias, float* __restrict__ Cout,
               __half* __restrict__ cth, int Mtot) {
    float acc[4][4][4];
    #pragma unroll
    for (int i = 0; i < 4; i++)
        #pragma unroll
        for (int j = 0; j < 4; j++)
            #pragma unroll
            for (int q = 0; q < 4; q++) acc[i][j][q] = 0.f;

    const int m0 = blockIdx.y * BM, n0 = blockIdx.x * BN;
    mm_loop<2>(acc, g_xhi, g_xlo, g_whi, HDIM, HDIM, m0, n0, 0, HDIM / BK);

    extern __shared__ char dsm[];
    uint32_t raw = smem_u32(dsm);
    char* smp = dsm + (((raw + 1023) & ~1023u) - raw);

    const int lane = threadIdx.x & 31, wid = threadIdx.x >> 5;
    const int wm = (wid >> 2) * 64, wn = (wid & 3) * 32;
    const int rl = lane >> 2;
    const int cl = (lane & 3) * 2;
    const int rbase = m0 + wm + rl;
    const int cbase = n0 + wn + cl;

    __half* tb = (__half*)(smp) + (size_t)wid * (32 * 66);

    __syncthreads();   // pipeline smem fully consumed before reuse
    #pragma unroll
    for (int mi = 0; mi < 4; mi++)
        #pragma unroll
        for (int ni = 0; ni < 4; ni++) {
            int r = rbase + mi * 16, cc = cbase + ni * 8;
            float2 bv = *(const float2*)(bias + cc);
            float v0 = acc[mi][ni][0] + bv.x, v1 = acc[mi][ni][1] + bv.y;
            float v2 = acc[mi][ni][2] + bv.x, v3 = acc[mi][ni][3] + bv.y;
            *(float2*)(Cout + (size_t)r * HDIM + cc)       = make_float2(v0, v1);
            *(float2*)(Cout + (size_t)(r + 8) * HDIM + cc) = make_float2(v2, v3);
            int lr = rl + mi * 16;
            int lc = cl + ni * 8;
            tb[(lc + 0) * 66 + lr]     = __float2half(v0);
            tb[(lc + 1) * 66 + lr]     = __float2half(v1);
            tb[(lc + 0) * 66 + lr + 8] = __float2half(v2);
            tb[(lc + 1) * 66 + lr + 8] = __float2half(v3);
        }
    __syncwarp();
    {
        const uint32_t* src = (const uint32_t*)(tb + lane * 66);
        size_t n = (size_t)(n0 + wn + lane);
        __half* dst = cth + n * Mtot + m0 + wm;
        #pragma unroll
        for (int j = 0; j < 8; j++) {
            uint4 v;
            v.x = src[j * 4 + 0]; v.y = src[j * 4 + 1];
            v.z = src[j * 4 + 2]; v.w = src[j * 4 + 3];
            *(uint4*)(dst + j * 8) = v;
        }
    }
}

// ---------------- GEMM2 partial: P[s] = Xhi^T @ Chi over k-split s ----------
__global__ __launch_bounds__(256, 2)
void gemm2_mma(int M) {
    float acc[4][4][4];
    #pragma unroll
    for (int i = 0; i < 4; i++)
        #pragma unroll
        for (int j = 0; j < 4; j++)
            #pragma unroll
            for (int q = 0; q < 4; q++) acc[i][j][q] = 0.f;

    const int s = blockIdx.z;
    const int kper = M / NSPLIT;
    const int h0 = blockIdx.y * BM, n0 = blockIdx.x * BN;
    mm_loop<1>(acc, g_xthi, (const __half*)0, g_cthi, M, M, h0, n0, s * kper, kper / BK);

    float* P = g_part + (size_t)s * HDIM * HDIM;
    const int lane = threadIdx.x & 31, wid = threadIdx.x >> 5;
    const int wm = (wid >> 2) * 64, wn = (wid & 3) * 32;
    const int rbase = h0 + wm + (lane >> 2);
    const int cbase = n0 + wn + (lane & 3) * 2;
    #pragma unroll
    for (int mi = 0; mi < 4; mi++)
        #pragma unroll
        for (int ni = 0; ni < 4; ni++) {
            int r = rbase + mi * 16, cc = cbase + ni * 8;
            *(float2*)(P + (size_t)r * HDIM + cc) =
                make_float2(acc[mi][ni][0], acc[mi][ni][1]);
            *(float2*)(P + (size_t)(r + 8) * HDIM + cc) =
                make_float2(acc[mi][ni][2], acc[mi][ni][3]);
        }
}

// ---------------- combine + norm + scale ----------------
__global__ void combine_kernel(const float* __restrict__ plastic,
                               const float* __restrict__ rate,
                               const float* __restrict__ hs,
                               float* __restrict__ Wout, float invM) {
    size_t i = (size_t)blockIdx.x * blockDim.x + threadIdx.x;   // float4 index
    const float factor = rate[0] * hs[0] * invM;
    const size_t stride4 = (size_t)HDIM * HDIM / 4;
    float4 s0 = ((const float4*)g_part)[i];
    float4 s1 = ((const float4*)g_part)[i + stride4];
    float4 s2 = ((const float4*)g_part)[i + 2 * stride4];
    float4 s3 = ((const float4*)g_part)[i + 3 * stride4];
    float4 p  = ((const float4*)plastic)[i];
    float4 o;
    o.x = p.x + factor * (s0.x + s1.x + s2.x + s3.x);
    o.y = p.y + factor * (s0.y + s1.y + s2.y + s3.y);
    o.z = p.z + factor * (s0.z + s1.z + s2.z + s3.z);
    o.w = p.w + factor * (s0.w + s1.w + s2.w + s3.w);
    ((float4*)Wout)[i] = o;
}

__global__ void sumsq_kernel(const float* __restrict__ W) {
    __shared__ double sh[256];
    const int tid = threadIdx.x;
    const float4* W4 = (const float4*)W;
    const size_t total4 = (size_t)HDIM * HDIM / 4;
    double s = 0.0;
    for (size_t i = (size_t)blockIdx.x * 256 + tid; i < total4;
         i += (size_t)gridDim.x * 256) {
        float4 v = W4[i];
        s += (double)v.x * v.x + (double)v.y * v.y
           + (double)v.z * v.z + (double)v.w * v.w;
    }
    sh[tid] = s;
    __syncthreads();
    for (int off = 128; off > 0; off >>= 1) {
        if (tid < off) sh[tid] += sh[tid + off];
        __syncthreads();
    }
    if (tid == 0) g_partials[blockIdx.x] = sh[0];
}

__global__ void finalize_kernel() {
    __shared__ double sh[256];
    const int tid = threadIdx.x;
    double s = 0.0;
    for (int i = tid; i < NRED; i += 256) s += g_partials[i];
    sh[tid] = s;
    __syncthreads();
    for (int off = 128; off > 0; off >>= 1) {
        if (tid < off) sh[tid] += sh[tid + off];
        __syncthreads();
    }
    if (tid == 0) {
        double norm = sqrt(sh[0]);
        g_scale = (norm > 1.0) ? (float)(1.0 / norm) : 1.0f;
    }
}

__global__ void scale_kernel(float* __restrict__ W) {
    size_t i = (size_t)blockIdx.x * blockDim.x + threadIdx.x;
    const float s = g_scale;
    float4 v = ((float4*)W)[i];
    v.x *= s; v.y *= s; v.z *= s; v.w *= s;
    ((float4*)W)[i] = v;
}

// ---------------- launch ----------------
extern "C" void kernel_launch(void* const* d_in, const int* in_sizes, int n_in,
                              void* d_out, int out_size) {
    const float* x    = (const float*)d_in[0];  // [M, H]
    const float* pw   = (const float*)d_in[1];  // [H, H]
    const float* rate = (const float*)d_in[2];  // [1]
    const float* fw   = (const float*)d_in[3];  // [H, H]
    const float* fb   = (const float*)d_in[4];  // [H]
    const float* hs   = (const float*)d_in[5];  // scalar

    const int M = in_sizes[0] / HDIM;           // 16384
    float* combined = (float*)d_out;
    float* neww     = (float*)d_out + (size_t)M * HDIM;

    static bool attr_done = false;
    if (!attr_done) {
        cudaFuncSetAttribute(gemm1_mma, cudaFuncAttributeMaxDynamicSharedMemorySize, SMEM1);
        cudaFuncSetAttribute(gemm2_mma, cudaFuncAttributeMaxDynamicSharedMemorySize, SMEM2);
        attr_done = true;
    }

    __half *xhi, *xlo, *xthi, *whi, *cthi;
    cudaGetSymbolAddress((void**)&xhi,  g_xhi);
    cudaGetSymbolAddress((void**)&xlo,  g_xlo);
    cudaGetSymbolAddress((void**)&xthi, g_xthi);
    cudaGetSymbolAddress((void**)&whi,  g_whi);
    cudaGetSymbolAddress((void**)&cthi, g_cthi);

    // operand prep: wsum (hi) + fused x split / transpose-hi
    wsum_hi_kernel<<<HDIM * HDIM / 4 / 256, 256>>>(fw, pw, whi);
    {
        dim3 g(HDIM / 32, M / 32);
        xprep_kernel<<<g, 256>>>(x, xhi, xlo, xthi, M, HDIM);
    }

    // GEMM1 (writes combined fp32 + combined^T fp16-hi)
    {
        dim3 g(HDIM / BN, M / BM);
        gemm1_mma<<<g, 256, SMEM1>>>(fb, combined, cthi, M);
    }

    // GEMM2 split-K partials (single product), then deterministic combine
    {
        dim3 g(HDIM / BN, HDIM / BM, NSPLIT);
        gemm2_mma<<<g, 256, SMEM2>>>(M);
    }
    combine_kernel<<<HDIM * HDIM / 4 / 256, 256>>>(pw, rate, hs, neww, 1.0f / (float)M);

    sumsq_kernel<<<NRED, 256>>>(neww);
    finalize_kernel<<<1, 256>>>();
    scale_kernel<<<HDIM * HDIM / 4 / 256, 256>>>(neww);
}

// round 10
// speedup vs baseline: 2.8830x; 1.4600x over previous
#include <cuda_runtime.h>
#include <cuda_fp16.h>
#include <cstdint>

#define HDIM  2048
#define MROWS 16384
#define BM    128
#define BN    128
#define BK    64
#define NSPLIT 4
#define NRED  4096   // combine grid size (one partial per block)

#define TILE_BYTES  (128 * 128)          // 16KB: 128 rows x 128B (64 fp16)
#define STAGE       (2 * TILE_BYTES)     // stage: Ahi Bhi (32KB)
#define SMEM_DYN    (3 * STAGE + 1024)   // 3-stage pipeline (97KB); occ=2 fits

// ---------------- device scratch (no allocs allowed) ----------------
__device__ __half g_xhi [(size_t)MROWS * HDIM];
__device__ __half g_xthi[(size_t)MROWS * HDIM];   // x^T [H, M]
__device__ __half g_whi [(size_t)HDIM * HDIM];    // fp16(fw+pw)
__device__ __half g_cthi[(size_t)MROWS * HDIM];   // combined^T [H, M] (fp16)
__device__ float  g_part[(size_t)NSPLIT * HDIM * HDIM];  // split-K partials
__device__ double g_partials[NRED];
__device__ float  g_scale;

// ---------------- PTX helpers (baseline sm_80+ features only) ----------------
__device__ __forceinline__ uint32_t smem_u32(const void* p) {
    uint32_t a;
    asm("{ .reg .u64 t; cvta.to.shared.u64 t, %1; cvt.u32.u64 %0, t; }" : "=r"(a) : "l"(p));
    return a;
}
__device__ __forceinline__ uint32_t sw128(uint32_t o) { return o ^ ((o >> 3) & 0x70); }

__device__ __forceinline__ void cpasync16(uint32_t d, const void* s) {
    asm volatile("cp.async.cg.shared.global [%0], [%1], 16;" :: "r"(d), "l"(s));
}
#define CP_COMMIT() asm volatile("cp.async.commit_group;" ::: "memory")
#define CP_WAIT2()  asm volatile("cp.async.wait_group 2;" ::: "memory")
#define CP_WAIT1()  asm volatile("cp.async.wait_group 1;" ::: "memory")
#define CP_WAIT0()  asm volatile("cp.async.wait_group 0;" ::: "memory")

__device__ __forceinline__ void ldsm4(uint32_t* r, uint32_t addr) {
    asm volatile("ldmatrix.sync.aligned.m8n8.x4.shared.b16 {%0,%1,%2,%3}, [%4];"
                 : "=r"(r[0]), "=r"(r[1]), "=r"(r[2]), "=r"(r[3]) : "r"(addr));
}
__device__ __forceinline__ void mma16816(float* c, const uint32_t* a, const uint32_t* b) {
    asm volatile(
        "mma.sync.aligned.m16n8k16.row.col.f32.f16.f16.f32 "
        "{%0,%1,%2,%3}, {%4,%5,%6,%7}, {%8,%9}, {%0,%1,%2,%3};"
        : "+f"(c[0]), "+f"(c[1]), "+f"(c[2]), "+f"(c[3])
        : "r"(a[0]), "r"(a[1]), "r"(a[2]), "r"(a[3]), "r"(b[0]), "r"(b[1]));
}

// ---------------- prep kernels ----------------
// Fused: read x [R,C] once per 32x32 tile; emit row-major fp16 (xhi)
// and transposed fp16 (xthi [C,R]).
__global__ void xprep_kernel(const float* __restrict__ in,
                             __half* __restrict__ rh, __half* __restrict__ th,
                             int R, int C) {
    __shared__ float t[32][33];
    int tid = threadIdx.x;                 // 256
    int r0 = blockIdx.y * 32, c0 = blockIdx.x * 32;
    int row = tid >> 3, seg = tid & 7;
    float4 v = *(const float4*)(in + (size_t)(r0 + row) * C + c0 + seg * 4);
    {
        size_t ob = ((size_t)(r0 + row) * C + c0 + seg * 4) >> 1;
        __half2* ph = (__half2*)rh + ob;
        ph[0] = __halves2half2(__float2half(v.x), __float2half(v.y));
        ph[1] = __halves2half2(__float2half(v.z), __float2half(v.w));
    }
    t[row][seg * 4 + 0] = v.x; t[row][seg * 4 + 1] = v.y;
    t[row][seg * 4 + 2] = v.z; t[row][seg * 4 + 3] = v.w;
    __syncthreads();
    int oc = row;
    int rs = seg * 4;
    __half h0 = __float2half(t[rs + 0][oc]);
    __half h1 = __float2half(t[rs + 1][oc]);
    __half h2 = __float2half(t[rs + 2][oc]);
    __half h3 = __float2half(t[rs + 3][oc]);
    size_t ob = ((size_t)(c0 + oc) * R + r0 + rs) >> 1;
    __half2* ph = (__half2*)th + ob;
    ph[0] = __halves2half2(h0, h1); ph[1] = __halves2half2(h2, h3);
}

__global__ void wsum_hi_kernel(const float* __restrict__ fw, const float* __restrict__ pw,
                               __half* __restrict__ oh) {
    size_t i = (size_t)blockIdx.x * blockDim.x + threadIdx.x;
    float4 a = ((const float4*)fw)[i];
    float4 b = ((const float4*)pw)[i];
    __half2* ph = (__half2*)oh + i * 2;
    ph[0] = __halves2half2(__float2half(a.x + b.x), __float2half(a.y + b.y));
    ph[1] = __halves2half2(__float2half(a.z + b.z), __float2half(a.w + b.w));
}

// ---------------- HMMA mainloop: single-product fp16, 3-stage pipeline ------
// D[m,n] = sum_k A[m,k] * B[n,k]   (stage = A B)
__device__ __forceinline__ void mm_loop(float acc[4][4][4],
    const __half* __restrict__ A, const __half* __restrict__ B,
    int lda, int ldb, int m0, int n0, int kbeg, int NC)
{
    constexpr uint32_t A_OFF = 0;
    constexpr uint32_t B_OFF = TILE_BYTES;

    extern __shared__ char dsm[];
    uint32_t raw = smem_u32(dsm);
    uint32_t sbase = (raw + 1023) & ~1023u;

    const int tid  = threadIdx.x;
    const int lane = tid & 31;
    const int wid  = tid >> 5;
    const int wm = (wid >> 2) * 64;
    const int wn = (wid & 3) * 32;

    const int arow  = wm + (lane & 15);
    const int akadd = (lane >> 4) << 3;
    const int nrow  = wn + (lane & 7) + ((lane >> 4) << 3);
    const int bkadd = ((lane >> 3) & 1) << 3;

    auto issue = [&](int c) {
        uint32_t sb = sbase + (uint32_t)(c % 3) * STAGE;
        const int k0 = kbeg + c * BK;
        #pragma unroll
        for (int t = 0; t < 4; t++) {
            int seg = tid + t * 256;
            int r = seg >> 3, sc = seg & 7;
            uint32_t so = sw128((uint32_t)(r * 128 + sc * 16));
            size_t ga = (size_t)(m0 + r) * lda + k0 + sc * 8;
            size_t gb = (size_t)(n0 + r) * ldb + k0 + sc * 8;
            cpasync16(sb + A_OFF + so, A + ga);
            cpasync16(sb + B_OFF + so, B + gb);
        }
    };

    issue(0); CP_COMMIT();
    issue(1); CP_COMMIT();

    #pragma unroll 1
    for (int c = 0; c < NC; c++) {
        if (c + 2 < NC) { issue(c + 2); CP_COMMIT(); CP_WAIT2(); }
        else if (c + 1 < NC) { CP_WAIT1(); }
        else { CP_WAIT0(); }
        __syncthreads();

        uint32_t st = sbase + (uint32_t)(c % 3) * STAGE;
        #pragma unroll
        for (int ks = 0; ks < 4; ks++) {
            uint32_t ah[4][4], bh[4][2];
            #pragma unroll
            for (int mi = 0; mi < 4; mi++) {
                uint32_t off = sw128((uint32_t)((arow + mi * 16) * 128 + (ks * 16 + akadd) * 2));
                ldsm4(ah[mi], st + A_OFF + off);
            }
            #pragma unroll
            for (int ng = 0; ng < 2; ng++) {
                uint32_t off = sw128((uint32_t)((nrow + ng * 16) * 128 + (ks * 16 + bkadd) * 2));
                uint32_t q[4];
                ldsm4(q, st + B_OFF + off);
                bh[2*ng][0] = q[0]; bh[2*ng][1] = q[1];
                bh[2*ng+1][0] = q[2]; bh[2*ng+1][1] = q[3];
            }
            #pragma unroll
            for (int mi = 0; mi < 4; mi++)
                #pragma unroll
                for (int ni = 0; ni < 4; ni++)
                    mma16816(acc[mi][ni], ah[mi], bh[ni]);
        }
        __syncthreads();
    }
}

// ---------------- GEMM1: combined = xhi @ whi^T + bias; also writes
// combined^T (fp16) via per-warp SMEM transpose ----------------
__global__ __launch_bounds__(256, 2)
void gemm1_mma(const float* __restrict__ bias, float* __restrict__ Cout,
               __half* __restrict__ cth, int Mtot) {
    float acc[4][4][4];
    #pragma unroll
    for (int i = 0; i < 4; i++)
        #pragma unroll
        for (int j = 0; j < 4; j++)
            #pragma unroll
            for (int q = 0; q < 4; q++) acc[i][j][q] = 0.f;

    const int m0 = blockIdx.y * BM, n0 = blockIdx.x * BN;
    mm_loop(acc, g_xhi, g_whi, HDIM, HDIM, m0, n0, 0, HDIM / BK);

    extern __shared__ char dsm[];
    uint32_t raw = smem_u32(dsm);
    char* smp = dsm + (((raw + 1023) & ~1023u) - raw);

    const int lane = threadIdx.x & 31, wid = threadIdx.x >> 5;
    const int wm = (wid >> 2) * 64, wn = (wid & 3) * 32;
    const int rl = lane >> 2;
    const int cl = (lane & 3) * 2;
    const int rbase = m0 + wm + rl;
    const int cbase = n0 + wn + cl;

    __half* tb = (__half*)(smp) + (size_t)wid * (32 * 66);

    __syncthreads();   // pipeline smem fully consumed before reuse
    #pragma unroll
    for (int mi = 0; mi < 4; mi++)
        #pragma unroll
        for (int ni = 0; ni < 4; ni++) {
            int r = rbase + mi * 16, cc = cbase + ni * 8;
            float2 bv = *(const float2*)(bias + cc);
            float v0 = acc[mi][ni][0] + bv.x, v1 = acc[mi][ni][1] + bv.y;
            float v2 = acc[mi][ni][2] + bv.x, v3 = acc[mi][ni][3] + bv.y;
            *(float2*)(Cout + (size_t)r * HDIM + cc)       = make_float2(v0, v1);
            *(float2*)(Cout + (size_t)(r + 8) * HDIM + cc) = make_float2(v2, v3);
            int lr = rl + mi * 16;
            int lc = cl + ni * 8;
            tb[(lc + 0) * 66 + lr]     = __float2half(v0);
            tb[(lc + 1) * 66 + lr]     = __float2half(v1);
            tb[(lc + 0) * 66 + lr + 8] = __float2half(v2);
            tb[(lc + 1) * 66 + lr + 8] = __float2half(v3);
        }
    __syncwarp();
    {
        const uint32_t* src = (const uint32_t*)(tb + lane * 66);
        size_t n = (size_t)(n0 + wn + lane);
        __half* dst = cth + n * Mtot + m0 + wm;
        #pragma unroll
        for (int j = 0; j < 8; j++) {
            uint4 v;
            v.x = src[j * 4 + 0]; v.y = src[j * 4 + 1];
            v.z = src[j * 4 + 2]; v.w = src[j * 4 + 3];
            *(uint4*)(dst + j * 8) = v;
        }
    }
}

// ---------------- GEMM2 partial: P[s] = Xhi^T @ Chi over k-split s ----------
__global__ __launch_bounds__(256, 2)
void gemm2_mma(int M) {
    float acc[4][4][4];
    #pragma unroll
    for (int i = 0; i < 4; i++)
        #pragma unroll
        for (int j = 0; j < 4; j++)
            #pragma unroll
            for (int q = 0; q < 4; q++) acc[i][j][q] = 0.f;

    const int s = blockIdx.z;
    const int kper = M / NSPLIT;
    const int h0 = blockIdx.y * BM, n0 = blockIdx.x * BN;
    mm_loop(acc, g_xthi, g_cthi, M, M, h0, n0, s * kper, kper / BK);

    float* P = g_part + (size_t)s * HDIM * HDIM;
    const int lane = threadIdx.x & 31, wid = threadIdx.x >> 5;
    const int wm = (wid >> 2) * 64, wn = (wid & 3) * 32;
    const int rbase = h0 + wm + (lane >> 2);
    const int cbase = n0 + wn + (lane & 3) * 2;
    #pragma unroll
    for (int mi = 0; mi < 4; mi++)
        #pragma unroll
        for (int ni = 0; ni < 4; ni++) {
            int r = rbase + mi * 16, cc = cbase + ni * 8;
            *(float2*)(P + (size_t)r * HDIM + cc) =
                make_float2(acc[mi][ni][0], acc[mi][ni][1]);
            *(float2*)(P + (size_t)(r + 8) * HDIM + cc) =
                make_float2(acc[mi][ni][2], acc[mi][ni][3]);
        }
}

// ---------------- combine (+ fused sumsq partials) + norm + scale -----------
__global__ void combine_kernel(const float* __restrict__ plastic,
                               const float* __restrict__ rate,
                               const float* __restrict__ hs,
                               float* __restrict__ Wout, float invM) {
    __shared__ double sh[256];
    size_t i = (size_t)blockIdx.x * blockDim.x + threadIdx.x;   // float4 index
    const float factor = rate[0] * hs[0] * invM;
    const size_t stride4 = (size_t)HDIM * HDIM / 4;
    float4 s0 = ((const float4*)g_part)[i];
    float4 s1 = ((const float4*)g_part)[i + stride4];
    float4 s2 = ((const float4*)g_part)[i + 2 * stride4];
    float4 s3 = ((const float4*)g_part)[i + 3 * stride4];
    float4 p  = ((const float4*)plastic)[i];
    float4 o;
    o.x = p.x + factor * (s0.x + s1.x + s2.x + s3.x);
    o.y = p.y + factor * (s0.y + s1.y + s2.y + s3.y);
    o.z = p.z + factor * (s0.z + s1.z + s2.z + s3.z);
    o.w = p.w + factor * (s0.w + s1.w + s2.w + s3.w);
    ((float4*)Wout)[i] = o;
    // fused sum-of-squares partial
    double s = (double)o.x * o.x + (double)o.y * o.y
             + (double)o.z * o.z + (double)o.w * o.w;
    sh[threadIdx.x] = s;
    __syncthreads();
    for (int off = 128; off > 0; off >>= 1) {
        if (threadIdx.x < off) sh[threadIdx.x] += sh[threadIdx.x + off];
        __syncthreads();
    }
    if (threadIdx.x == 0) g_partials[blockIdx.x] = sh[0];
}

__global__ void finalize_kernel() {
    __shared__ double sh[256];
    const int tid = threadIdx.x;
    double s = 0.0;
    for (int i = tid; i < NRED; i += 256) s += g_partials[i];
    sh[tid] = s;
    __syncthreads();
    for (int off = 128; off > 0; off >>= 1) {
        if (tid < off) sh[tid] += sh[tid + off];
        __syncthreads();
    }
    if (tid == 0) {
        double norm = sqrt(sh[0]);
        g_scale = (norm > 1.0) ? (float)(1.0 / norm) : 1.0f;
    }
}

__global__ void scale_kernel(float* __restrict__ W) {
    size_t i = (size_t)blockIdx.x * blockDim.x + threadIdx.x;
    const float s = g_scale;
    float4 v = ((float4*)W)[i];
    v.x *= s; v.y *= s; v.z *= s; v.w *= s;
    ((float4*)W)[i] = v;
}

// ---------------- launch ----------------
extern "C" void kernel_launch(void* const* d_in, const int* in_sizes, int n_in,
                              void* d_out, int out_size) {
    const float* x    = (const float*)d_in[0];  // [M, H]
    const float* pw   = (const float*)d_in[1];  // [H, H]
    const float* rate = (const float*)d_in[2];  // [1]
    const float* fw   = (const float*)d_in[3];  // [H, H]
    const float* fb   = (const float*)d_in[4];  // [H]
    const float* hs   = (const float*)d_in[5];  // scalar

    const int M = in_sizes[0] / HDIM;           // 16384
    float* combined = (float*)d_out;
    float* neww     = (float*)d_out + (size_t)M * HDIM;

    static bool attr_done = false;
    if (!attr_done) {
        cudaFuncSetAttribute(gemm1_mma, cudaFuncAttributeMaxDynamicSharedMemorySize, SMEM_DYN);
        cudaFuncSetAttribute(gemm2_mma, cudaFuncAttributeMaxDynamicSharedMemorySize, SMEM_DYN);
        attr_done = true;
    }

    __half *xhi, *xthi, *whi, *cthi;
    cudaGetSymbolAddress((void**)&xhi,  g_xhi);
    cudaGetSymbolAddress((void**)&xthi, g_xthi);
    cudaGetSymbolAddress((void**)&whi,  g_whi);
    cudaGetSymbolAddress((void**)&cthi, g_cthi);

    // operand prep: wsum (fp16) + fused x fp16 / transpose
    wsum_hi_kernel<<<HDIM * HDIM / 4 / 256, 256>>>(fw, pw, whi);
    {
        dim3 g(HDIM / 32, M / 32);
        xprep_kernel<<<g, 256>>>(x, xhi, xthi, M, HDIM);
    }

    // GEMM1 (writes combined fp32 + combined^T fp16)
    {
        dim3 g(HDIM / BN, M / BM);
        gemm1_mma<<<g, 256, SMEM_DYN>>>(fb, combined, cthi, M);
    }

    // GEMM2 split-K partials, then combine (+ fused norm partials)
    {
        dim3 g(HDIM / BN, HDIM / BM, NSPLIT);
        gemm2_mma<<<g, 256, SMEM_DYN>>>(M);
    }
    combine_kernel<<<NRED, 256>>>(pw, rate, hs, neww, 1.0f / (float)M);

    finalize_kernel<<<1, 256>>>();
    scale_kernel<<<HDIM * HDIM / 4 / 256, 256>>>(neww);
}

// round 11
// speedup vs baseline: 3.3598x; 1.1654x over previous
#include <cuda_runtime.h>
#include <cuda_fp16.h>
#include <cstdint>

#define HDIM  2048
#define MROWS 16384
#define BM    128
#define BN    128
#define BK    64
#define KSPLIT 2          // split-K for symmetric X^T X
#define NTILE (HDIM / BM) // 16
#define NTRI  (NTILE * (NTILE + 1) / 2)   // 136
#define NRED  (NTILE * NTILE)             // 256 (gemm3 grid)

#define TILE_BYTES  (128 * 128)          // 16KB: 128 rows x 128B (64 fp16)
#define STAGE       (2 * TILE_BYTES)     // stage: A B (32KB)
#define SMEM_DYN    (3 * STAGE + 1024)   // 3-stage pipeline (~97KB); occ=2 fits

// ---------------- device scratch (no allocs allowed) ----------------
__device__ __half g_xhi [(size_t)MROWS * HDIM];
__device__ __half g_xthi[(size_t)MROWS * HDIM];   // x^T [H, M] fp16
__device__ __half g_whi [(size_t)HDIM * HDIM];    // fp16(fw+pw)
__device__ __half g_ghi [(size_t)HDIM * HDIM];    // fp16(G = X^T X)
__device__ float  g_part[(size_t)KSPLIT * HDIM * HDIM];  // G split-K partials
__device__ float  g_colsum[HDIM];                 // colsum(X)
__device__ double g_partials[NRED];
__device__ float  g_scale;

// ---------------- PTX helpers (baseline sm_80+ features only) ----------------
__device__ __forceinline__ uint32_t smem_u32(const void* p) {
    uint32_t a;
    asm("{ .reg .u64 t; cvta.to.shared.u64 t, %1; cvt.u32.u64 %0, t; }" : "=r"(a) : "l"(p));
    return a;
}
__device__ __forceinline__ uint32_t sw128(uint32_t o) { return o ^ ((o >> 3) & 0x70); }

__device__ __forceinline__ void cpasync16(uint32_t d, const void* s) {
    asm volatile("cp.async.cg.shared.global [%0], [%1], 16;" :: "r"(d), "l"(s));
}
#define CP_COMMIT() asm volatile("cp.async.commit_group;" ::: "memory")
#define CP_WAIT2()  asm volatile("cp.async.wait_group 2;" ::: "memory")
#define CP_WAIT1()  asm volatile("cp.async.wait_group 1;" ::: "memory")
#define CP_WAIT0()  asm volatile("cp.async.wait_group 0;" ::: "memory")

__device__ __forceinline__ void ldsm4(uint32_t* r, uint32_t addr) {
    asm volatile("ldmatrix.sync.aligned.m8n8.x4.shared.b16 {%0,%1,%2,%3}, [%4];"
                 : "=r"(r[0]), "=r"(r[1]), "=r"(r[2]), "=r"(r[3]) : "r"(addr));
}
__device__ __forceinline__ void mma16816(float* c, const uint32_t* a, const uint32_t* b) {
    asm volatile(
        "mma.sync.aligned.m16n8k16.row.col.f32.f16.f16.f32 "
        "{%0,%1,%2,%3}, {%4,%5,%6,%7}, {%8,%9}, {%0,%1,%2,%3};"
        : "+f"(c[0]), "+f"(c[1]), "+f"(c[2]), "+f"(c[3])
        : "r"(a[0]), "r"(a[1]), "r"(a[2]), "r"(a[3]), "r"(b[0]), "r"(b[1]));
}

// ---------------- prep kernels ----------------
__global__ void xprep_kernel(const float* __restrict__ in,
                             __half* __restrict__ rh, __half* __restrict__ th,
                             int R, int C) {
    __shared__ float t[32][33];
    int tid = threadIdx.x;                 // 256
    int r0 = blockIdx.y * 32, c0 = blockIdx.x * 32;
    int row = tid >> 3, seg = tid & 7;
    float4 v = *(const float4*)(in + (size_t)(r0 + row) * C + c0 + seg * 4);
    {
        size_t ob = ((size_t)(r0 + row) * C + c0 + seg * 4) >> 1;
        __half2* ph = (__half2*)rh + ob;
        ph[0] = __halves2half2(__float2half(v.x), __float2half(v.y));
        ph[1] = __halves2half2(__float2half(v.z), __float2half(v.w));
    }
    t[row][seg * 4 + 0] = v.x; t[row][seg * 4 + 1] = v.y;
    t[row][seg * 4 + 2] = v.z; t[row][seg * 4 + 3] = v.w;
    __syncthreads();
    int oc = row;
    int rs = seg * 4;
    __half h0 = __float2half(t[rs + 0][oc]);
    __half h1 = __float2half(t[rs + 1][oc]);
    __half h2 = __float2half(t[rs + 2][oc]);
    __half h3 = __float2half(t[rs + 3][oc]);
    size_t ob = ((size_t)(c0 + oc) * R + r0 + rs) >> 1;
    __half2* ph = (__half2*)th + ob;
    ph[0] = __halves2half2(h0, h1); ph[1] = __halves2half2(h2, h3);
}

__global__ void wsum_hi_kernel(const float* __restrict__ fw, const float* __restrict__ pw,
                               __half* __restrict__ oh) {
    size_t i = (size_t)blockIdx.x * blockDim.x + threadIdx.x;
    float4 a = ((const float4*)fw)[i];
    float4 b = ((const float4*)pw)[i];
    __half2* ph = (__half2*)oh + i * 2;
    ph[0] = __halves2half2(__float2half(a.x + b.x), __float2half(a.y + b.y));
    ph[1] = __halves2half2(__float2half(a.z + b.z), __float2half(a.w + b.w));
}

// colsum over x^T rows: s[h] = sum_m xthi[h][m]  (one block per h)
__global__ void colsum_kernel(const __half* __restrict__ xt, float* __restrict__ s, int M) {
    __shared__ float sh[256];
    const int h = blockIdx.x, tid = threadIdx.x;
    const __half2* row = (const __half2*)(xt + (size_t)h * M);
    float acc = 0.f;
    for (int i = tid; i < M / 2; i += 256) {
        float2 v = __half22float2(row[i]);
        acc += v.x + v.y;
    }
    sh[tid] = acc;
    __syncthreads();
    for (int off = 128; off > 0; off >>= 1) {
        if (tid < off) sh[tid] += sh[tid + off];
        __syncthreads();
    }
    if (tid == 0) s[h] = sh[0];
}

// G = P0 + P1 -> fp16
__global__ void gsum_hi_kernel(__half* __restrict__ gh) {
    size_t i = (size_t)blockIdx.x * blockDim.x + threadIdx.x;   // float4 index
    const size_t stride4 = (size_t)HDIM * HDIM / 4;
    float4 a = ((const float4*)g_part)[i];
    float4 b = ((const float4*)g_part)[i + stride4];
    __half2* ph = (__half2*)gh + i * 2;
    ph[0] = __halves2half2(__float2half(a.x + b.x), __float2half(a.y + b.y));
    ph[1] = __halves2half2(__float2half(a.z + b.z), __float2half(a.w + b.w));
}

// ---------------- HMMA mainloop: single-product fp16, 3-stage pipeline ------
__device__ __forceinline__ void mm_loop(float acc[4][4][4],
    const __half* __restrict__ A, const __half* __restrict__ B,
    int lda, int ldb, int m0, int n0, int kbeg, int NC)
{
    constexpr uint32_t A_OFF = 0;
    constexpr uint32_t B_OFF = TILE_BYTES;

    extern __shared__ char dsm[];
    uint32_t raw = smem_u32(dsm);
    uint32_t sbase = (raw + 1023) & ~1023u;

    const int tid  = threadIdx.x;
    const int lane = tid & 31;
    const int wid  = tid >> 5;
    const int wm = (wid >> 2) * 64;
    const int wn = (wid & 3) * 32;

    const int arow  = wm + (lane & 15);
    const int akadd = (lane >> 4) << 3;
    const int nrow  = wn + (lane & 7) + ((lane >> 4) << 3);
    const int bkadd = ((lane >> 3) & 1) << 3;

    auto issue = [&](int c) {
        uint32_t sb = sbase + (uint32_t)(c % 3) * STAGE;
        const int k0 = kbeg + c * BK;
        #pragma unroll
        for (int t = 0; t < 4; t++) {
            int seg = tid + t * 256;
            int r = seg >> 3, sc = seg & 7;
            uint32_t so = sw128((uint32_t)(r * 128 + sc * 16));
            size_t ga = (size_t)(m0 + r) * lda + k0 + sc * 8;
            size_t gb = (size_t)(n0 + r) * ldb + k0 + sc * 8;
            cpasync16(sb + A_OFF + so, A + ga);
            cpasync16(sb + B_OFF + so, B + gb);
        }
    };

    issue(0); CP_COMMIT();
    issue(1); CP_COMMIT();

    #pragma unroll 1
    for (int c = 0; c < NC; c++) {
        if (c + 2 < NC) { issue(c + 2); CP_COMMIT(); CP_WAIT2(); }
        else if (c + 1 < NC) { CP_WAIT1(); }
        else { CP_WAIT0(); }
        __syncthreads();

        uint32_t st = sbase + (uint32_t)(c % 3) * STAGE;
        #pragma unroll
        for (int ks = 0; ks < 4; ks++) {
            uint32_t ah[4][4], bh[4][2];
            #pragma unroll
            for (int mi = 0; mi < 4; mi++) {
                uint32_t off = sw128((uint32_t)((arow + mi * 16) * 128 + (ks * 16 + akadd) * 2));
                ldsm4(ah[mi], st + A_OFF + off);
            }
            #pragma unroll
            for (int ng = 0; ng < 2; ng++) {
                uint32_t off = sw128((uint32_t)((nrow + ng * 16) * 128 + (ks * 16 + bkadd) * 2));
                uint32_t q[4];
                ldsm4(q, st + B_OFF + off);
                bh[2*ng][0] = q[0]; bh[2*ng][1] = q[1];
                bh[2*ng+1][0] = q[2]; bh[2*ng+1][1] = q[3];
            }
            #pragma unroll
            for (int mi = 0; mi < 4; mi++)
                #pragma unroll
                for (int ni = 0; ni < 4; ni++)
                    mma16816(acc[mi][ni], ah[mi], bh[ni]);
        }
        __syncthreads();
    }
}

#define ACC_INIT(acc) \
    _Pragma("unroll") for (int i = 0; i < 4; i++) \
    _Pragma("unroll") for (int j = 0; j < 4; j++) \
    _Pragma("unroll") for (int q = 0; q < 4; q++) acc[i][j][q] = 0.f;

// ---------------- GEMM1: combined = xhi @ whi^T + bias ----------------
__global__ __launch_bounds__(256, 2)
void gemm1_mma(const float* __restrict__ bias, float* __restrict__ Cout) {
    float acc[4][4][4];
    ACC_INIT(acc)
    const int m0 = blockIdx.y * BM, n0 = blockIdx.x * BN;
    mm_loop(acc, g_xhi, g_whi, HDIM, HDIM, m0, n0, 0, HDIM / BK);

    const int lane = threadIdx.x & 31, wid = threadIdx.x >> 5;
    const int wm = (wid >> 2) * 64, wn = (wid & 3) * 32;
    const int rbase = m0 + wm + (lane >> 2);
    const int cbase = n0 + wn + (lane & 3) * 2;
    #pragma unroll
    for (int mi = 0; mi < 4; mi++)
        #pragma unroll
        for (int ni = 0; ni < 4; ni++) {
            int r = rbase + mi * 16, cc = cbase + ni * 8;
            float2 bv = *(const float2*)(bias + cc);
            *(float2*)(Cout + (size_t)r * HDIM + cc) =
                make_float2(acc[mi][ni][0] + bv.x, acc[mi][ni][1] + bv.y);
            *(float2*)(Cout + (size_t)(r + 8) * HDIM + cc) =
                make_float2(acc[mi][ni][2] + bv.x, acc[mi][ni][3] + bv.y);
        }
}

// ---------------- GEMM2sym: P[s] += Xt[bi] @ Xt[bj]^T (lower triangle) ------
// Writes tile (bi,bj) directly and (bj,bi) transposed (off-diagonal only).
__global__ __launch_bounds__(256, 2)
void gemm2s_mma(int M) {
    float acc[4][4][4];
    ACC_INIT(acc)

    // triangular decode: blockIdx.x -> (bi, bj), bi >= bj
    int t = blockIdx.x;
    int bi = 0;
    while ((bi + 1) * (bi + 2) / 2 <= t) bi++;
    int bj = t - bi * (bi + 1) / 2;

    const int s = blockIdx.z;
    const int kper = M / KSPLIT;
    const int h0 = bi * BM, n0 = bj * BN;
    mm_loop(acc, g_xthi, g_xthi, M, M, h0, n0, s * kper, kper / BK);

    float* P = g_part + (size_t)s * HDIM * HDIM;
    const int lane = threadIdx.x & 31, wid = threadIdx.x >> 5;
    const int wm = (wid >> 2) * 64, wn = (wid & 3) * 32;
    const int rl = lane >> 2;
    const int cl = (lane & 3) * 2;

    // direct write: P[h0 + r][n0 + c]
    #pragma unroll
    for (int mi = 0; mi < 4; mi++)
        #pragma unroll
        for (int ni = 0; ni < 4; ni++) {
            int r = h0 + wm + rl + mi * 16, cc = n0 + wn + cl + ni * 8;
            *(float2*)(P + (size_t)r * HDIM + cc) =
                make_float2(acc[mi][ni][0], acc[mi][ni][1]);
            *(float2*)(P + (size_t)(r + 8) * HDIM + cc) =
                make_float2(acc[mi][ni][2], acc[mi][ni][3]);
        }

    if (bi != bj) {
        // transposed write via per-warp smem buffer [32 c][66 r]
        extern __shared__ char dsm[];
        uint32_t raw = smem_u32(dsm);
        char* smp = dsm + (((raw + 1023) & ~1023u) - raw);
        float* tb = (float*)smp + (size_t)wid * (32 * 66);
        __syncthreads();   // mainloop smem fully consumed
        #pragma unroll
        for (int mi = 0; mi < 4; mi++)
            #pragma unroll
            for (int ni = 0; ni < 4; ni++) {
                int lr = rl + mi * 16;
                int lc = cl + ni * 8;
                tb[(lc + 0) * 66 + lr]     = acc[mi][ni][0];
                tb[(lc + 1) * 66 + lr]     = acc[mi][ni][1];
                tb[(lc + 0) * 66 + lr + 8] = acc[mi][ni][2];
                tb[(lc + 1) * 66 + lr + 8] = acc[mi][ni][3];
            }
        __syncwarp();
        const float* src = tb + lane * 66;
        float* dst = P + (size_t)(n0 + wn + lane) * HDIM + h0 + wm;
        #pragma unroll
        for (int j = 0; j < 16; j++) {
            float4 v;
            v.x = src[j * 4 + 0]; v.y = src[j * 4 + 1];
            v.z = src[j * 4 + 2]; v.w = src[j * 4 + 3];
            *(float4*)(dst + j * 4) = v;
        }
    }
}

// ---------------- GEMM3: neww = plastic + factor*(G@Wsum^T + s b^T);
// epilogue also emits sum-of-squares partials ----------------
__global__ __launch_bounds__(256, 2)
void gemm3_mma(const float* __restrict__ plastic,
               const float* __restrict__ rate, const float* __restrict__ hs,
               const float* __restrict__ bias,
               float* __restrict__ Wout, float invM) {
    __shared__ double shred[256];
    float acc[4][4][4];
    ACC_INIT(acc)
    const int m0 = blockIdx.y * BM, n0 = blockIdx.x * BN;
    mm_loop(acc, g_ghi, g_whi, HDIM, HDIM, m0, n0, 0, HDIM / BK);

    const float factor = rate[0] * hs[0] * invM;
    const int lane = threadIdx.x & 31, wid = threadIdx.x >> 5;
    const int wm = (wid >> 2) * 64, wn = (wid & 3) * 32;
    const int rbase = m0 + wm + (lane >> 2);
    const int cbase = n0 + wn + (lane & 3) * 2;
    double ss = 0.0;
    #pragma unroll
    for (int mi = 0; mi < 4; mi++)
        #pragma unroll
        for (int ni = 0; ni < 4; ni++) {
            int r = rbase + mi * 16, cc = cbase + ni * 8;
            float2 bv = *(const float2*)(bias + cc);
            float s0 = g_colsum[r], s1 = g_colsum[r + 8];
            float2 p0 = *(const float2*)(plastic + (size_t)r * HDIM + cc);
            float2 p1 = *(const float2*)(plastic + (size_t)(r + 8) * HDIM + cc);
            float v0 = p0.x + factor * (acc[mi][ni][0] + s0 * bv.x);
            float v1 = p0.y + factor * (acc[mi][ni][1] + s0 * bv.y);
            float v2 = p1.x + factor * (acc[mi][ni][2] + s1 * bv.x);
            float v3 = p1.y + factor * (acc[mi][ni][3] + s1 * bv.y);
            *(float2*)(Wout + (size_t)r * HDIM + cc)       = make_float2(v0, v1);
            *(float2*)(Wout + (size_t)(r + 8) * HDIM + cc) = make_float2(v2, v3);
            ss += (double)v0 * v0 + (double)v1 * v1
                + (double)v2 * v2 + (double)v3 * v3;
        }
    shred[threadIdx.x] = ss;
    __syncthreads();
    for (int off = 128; off > 0; off >>= 1) {
        if (threadIdx.x < off) shred[threadIdx.x] += shred[threadIdx.x + off];
        __syncthreads();
    }
    if (threadIdx.x == 0)
        g_partials[blockIdx.y * NTILE + blockIdx.x] = shred[0];
}

// ---------------- norm finalize + scale ----------------
__global__ void finalize_kernel() {
    __shared__ double sh[256];
    const int tid = threadIdx.x;
    double s = (tid < NRED) ? g_partials[tid] : 0.0;
    sh[tid] = s;
    __syncthreads();
    for (int off = 128; off > 0; off >>= 1) {
        if (tid < off) sh[tid] += sh[tid + off];
        __syncthreads();
    }
    if (tid == 0) {
        double norm = sqrt(sh[0]);
        g_scale = (norm > 1.0) ? (float)(1.0 / norm) : 1.0f;
    }
}

__global__ void scale_kernel(float* __restrict__ W) {
    size_t i = (size_t)blockIdx.x * blockDim.x + threadIdx.x;
    const float s = g_scale;
    float4 v = ((float4*)W)[i];
    v.x *= s; v.y *= s; v.z *= s; v.w *= s;
    ((float4*)W)[i] = v;
}

// ---------------- launch ----------------
extern "C" void kernel_launch(void* const* d_in, const int* in_sizes, int n_in,
                              void* d_out, int out_size) {
    const float* x    = (const float*)d_in[0];  // [M, H]
    const float* pw   = (const float*)d_in[1];  // [H, H]
    const float* rate = (const float*)d_in[2];  // [1]
    const float* fw   = (const float*)d_in[3];  // [H, H]
    const float* fb   = (const float*)d_in[4];  // [H]
    const float* hs   = (const float*)d_in[5];  // scalar

    const int M = in_sizes[0] / HDIM;           // 16384
    float* combined = (float*)d_out;
    float* neww     = (float*)d_out + (size_t)M * HDIM;

    static bool attr_done = false;
    if (!attr_done) {
        cudaFuncSetAttribute(gemm1_mma,  cudaFuncAttributeMaxDynamicSharedMemorySize, SMEM_DYN);
        cudaFuncSetAttribute(gemm2s_mma, cudaFuncAttributeMaxDynamicSharedMemorySize, SMEM_DYN);
        cudaFuncSetAttribute(gemm3_mma,  cudaFuncAttributeMaxDynamicSharedMemorySize, SMEM_DYN);
        attr_done = true;
    }

    __half *xhi, *xthi, *whi, *ghi;
    float* cs;
    cudaGetSymbolAddress((void**)&xhi,  g_xhi);
    cudaGetSymbolAddress((void**)&xthi, g_xthi);
    cudaGetSymbolAddress((void**)&whi,  g_whi);
    cudaGetSymbolAddress((void**)&ghi,  g_ghi);
    cudaGetSymbolAddress((void**)&cs,   g_colsum);

    // prep
    wsum_hi_kernel<<<HDIM * HDIM / 4 / 256, 256>>>(fw, pw, whi);
    {
        dim3 g(HDIM / 32, M / 32);
        xprep_kernel<<<g, 256>>>(x, xhi, xthi, M, HDIM);
    }
    colsum_kernel<<<HDIM, 256>>>(xthi, cs, M);

    // G = X^T X (symmetric, split-K=2)
    {
        dim3 g(NTRI, 1, KSPLIT);
        gemm2s_mma<<<g, 256, SMEM_DYN>>>(M);
    }

    // GEMM1: combined (output 1)
    {
        dim3 g(HDIM / BN, M / BM);
        gemm1_mma<<<g, 256, SMEM_DYN>>>(fb, combined);
    }

    // G partials -> fp16, then GEMM3 (+combine fused) -> neww (output 2)
    gsum_hi_kernel<<<HDIM * HDIM / 4 / 256, 256>>>(ghi);
    {
        dim3 g(NTILE, NTILE);
        gemm3_mma<<<g, 256, SMEM_DYN>>>(pw, rate, hs, fb, neww, 1.0f / (float)M);
    }

    finalize_kernel<<<1, 256>>>();
    scale_kernel<<<HDIM * HDIM / 4 / 256, 256>>>(neww);
}

// round 12
// speedup vs baseline: 3.3988x; 1.0116x over previous
#include <cuda_runtime.h>
#include <cuda_fp16.h>
#include <cstdint>

#define HDIM  2048
#define MROWS 16384
#define BM    128
#define BN    128
#define BK    64
#define KSPLIT 2          // split-K for symmetric X^T X
#define NTILE (HDIM / BM) // 16
#define NTRI  (NTILE * (NTILE + 1) / 2)   // 136
#define NRED  (NTILE * NTILE)             // 256 (gemm3 grid)

#define TILE_BYTES  (128 * 128)          // 16KB: 128 rows x 128B (64 fp16)
#define STAGE       (2 * TILE_BYTES)     // stage: A B (32KB)
#define SMEM_DYN    (3 * STAGE + 1024)   // 3-stage pipeline (~97KB); occ=2 fits

// ---------------- device scratch (no allocs allowed) ----------------
__device__ __half g_xhi [(size_t)MROWS * HDIM];
__device__ __half g_xthi[(size_t)MROWS * HDIM];   // x^T [H, M] fp16
__device__ __half g_whi [(size_t)HDIM * HDIM];    // fp16(fw+pw)
__device__ __half g_ghi [(size_t)HDIM * HDIM];    // fp16(G = X^T X)
__device__ float  g_part[(size_t)KSPLIT * HDIM * HDIM];  // G split-K partials
__device__ float  g_colsum[HDIM];                 // colsum(X)
__device__ double g_partials[NRED];
__device__ float  g_scale;

// ---------------- PTX helpers (baseline sm_80+ features only) ----------------
__device__ __forceinline__ uint32_t smem_u32(const void* p) {
    uint32_t a;
    asm("{ .reg .u64 t; cvta.to.shared.u64 t, %1; cvt.u32.u64 %0, t; }" : "=r"(a) : "l"(p));
    return a;
}
__device__ __forceinline__ uint32_t sw128(uint32_t o) { return o ^ ((o >> 3) & 0x70); }

__device__ __forceinline__ void cpasync16(uint32_t d, const void* s) {
    asm volatile("cp.async.cg.shared.global [%0], [%1], 16;" :: "r"(d), "l"(s));
}
#define CP_COMMIT() asm volatile("cp.async.commit_group;" ::: "memory")
#define CP_WAIT2()  asm volatile("cp.async.wait_group 2;" ::: "memory")
#define CP_WAIT1()  asm volatile("cp.async.wait_group 1;" ::: "memory")
#define CP_WAIT0()  asm volatile("cp.async.wait_group 0;" ::: "memory")

__device__ __forceinline__ void ldsm4(uint32_t* r, uint32_t addr) {
    asm volatile("ldmatrix.sync.aligned.m8n8.x4.shared.b16 {%0,%1,%2,%3}, [%4];"
                 : "=r"(r[0]), "=r"(r[1]), "=r"(r[2]), "=r"(r[3]) : "r"(addr));
}
__device__ __forceinline__ void mma16816(float* c, const uint32_t* a, const uint32_t* b) {
    asm volatile(
        "mma.sync.aligned.m16n8k16.row.col.f32.f16.f16.f32 "
        "{%0,%1,%2,%3}, {%4,%5,%6,%7}, {%8,%9}, {%0,%1,%2,%3};"
        : "+f"(c[0]), "+f"(c[1]), "+f"(c[2]), "+f"(c[3])
        : "r"(a[0]), "r"(a[1]), "r"(a[2]), "r"(a[3]), "r"(b[0]), "r"(b[1]));
}

// ---------------- prep kernels ----------------
__global__ void xprep_kernel(const float* __restrict__ in,
                             __half* __restrict__ rh, __half* __restrict__ th,
                             int R, int C) {
    __shared__ float t[32][33];
    int tid = threadIdx.x;                 // 256
    int r0 = blockIdx.y * 32, c0 = blockIdx.x * 32;
    int row = tid >> 3, seg = tid & 7;
    float4 v = *(const float4*)(in + (size_t)(r0 + row) * C + c0 + seg * 4);
    {
        size_t ob = ((size_t)(r0 + row) * C + c0 + seg * 4) >> 1;
        __half2* ph = (__half2*)rh + ob;
        ph[0] = __halves2half2(__float2half(v.x), __float2half(v.y));
        ph[1] = __halves2half2(__float2half(v.z), __float2half(v.w));
    }
    t[row][seg * 4 + 0] = v.x; t[row][seg * 4 + 1] = v.y;
    t[row][seg * 4 + 2] = v.z; t[row][seg * 4 + 3] = v.w;
    __syncthreads();
    int oc = row;
    int rs = seg * 4;
    __half h0 = __float2half(t[rs + 0][oc]);
    __half h1 = __float2half(t[rs + 1][oc]);
    __half h2 = __float2half(t[rs + 2][oc]);
    __half h3 = __float2half(t[rs + 3][oc]);
    size_t ob = ((size_t)(c0 + oc) * R + r0 + rs) >> 1;
    __half2* ph = (__half2*)th + ob;
    ph[0] = __halves2half2(h0, h1); ph[1] = __halves2half2(h2, h3);
}

__global__ void wsum_hi_kernel(const float* __restrict__ fw, const float* __restrict__ pw,
                               __half* __restrict__ oh) {
    size_t i = (size_t)blockIdx.x * blockDim.x + threadIdx.x;
    float4 a = ((const float4*)fw)[i];
    float4 b = ((const float4*)pw)[i];
    __half2* ph = (__half2*)oh + i * 2;
    ph[0] = __halves2half2(__float2half(a.x + b.x), __float2half(a.y + b.y));
    ph[1] = __halves2half2(__float2half(a.z + b.z), __float2half(a.w + b.w));
}

// colsum over x^T rows: s[h] = sum_m xthi[h][m]  (one block per h)
__global__ void colsum_kernel(const __half* __restrict__ xt, float* __restrict__ s, int M) {
    __shared__ float sh[256];
    const int h = blockIdx.x, tid = threadIdx.x;
    const __half2* row = (const __half2*)(xt + (size_t)h * M);
    float acc = 0.f;
    for (int i = tid; i < M / 2; i += 256) {
        float2 v = __half22float2(row[i]);
        acc += v.x + v.y;
    }
    sh[tid] = acc;
    __syncthreads();
    for (int off = 128; off > 0; off >>= 1) {
        if (tid < off) sh[tid] += sh[tid + off];
        __syncthreads();
    }
    if (tid == 0) s[h] = sh[0];
}

// G = P0 + P1 -> fp16
__global__ void gsum_hi_kernel(__half* __restrict__ gh) {
    size_t i = (size_t)blockIdx.x * blockDim.x + threadIdx.x;   // float4 index
    const size_t stride4 = (size_t)HDIM * HDIM / 4;
    float4 a = ((const float4*)g_part)[i];
    float4 b = ((const float4*)g_part)[i + stride4];
    __half2* ph = (__half2*)gh + i * 2;
    ph[0] = __halves2half2(__float2half(a.x + b.x), __float2half(a.y + b.y));
    ph[1] = __halves2half2(__float2half(a.z + b.z), __float2half(a.w + b.w));
}

// ---------------- HMMA mainloop: single-product fp16, 3-stage pipeline ------
__device__ __forceinline__ void mm_loop(float acc[4][4][4],
    const __half* __restrict__ A, const __half* __restrict__ B,
    int lda, int ldb, int m0, int n0, int kbeg, int NC)
{
    constexpr uint32_t A_OFF = 0;
    constexpr uint32_t B_OFF = TILE_BYTES;

    extern __shared__ char dsm[];
    uint32_t raw = smem_u32(dsm);
    uint32_t sbase = (raw + 1023) & ~1023u;

    const int tid  = threadIdx.x;
    const int lane = tid & 31;
    const int wid  = tid >> 5;
    const int wm = (wid >> 2) * 64;
    const int wn = (wid & 3) * 32;

    const int arow  = wm + (lane & 15);
    const int akadd = (lane >> 4) << 3;
    const int nrow  = wn + (lane & 7) + ((lane >> 4) << 3);
    const int bkadd = ((lane >> 3) & 1) << 3;

    auto issue = [&](int c) {
        uint32_t sb = sbase + (uint32_t)(c % 3) * STAGE;
        const int k0 = kbeg + c * BK;
        #pragma unroll
        for (int t = 0; t < 4; t++) {
            int seg = tid + t * 256;
            int r = seg >> 3, sc = seg & 7;
            uint32_t so = sw128((uint32_t)(r * 128 + sc * 16));
            size_t ga = (size_t)(m0 + r) * lda + k0 + sc * 8;
            size_t gb = (size_t)(n0 + r) * ldb + k0 + sc * 8;
            cpasync16(sb + A_OFF + so, A + ga);
            cpasync16(sb + B_OFF + so, B + gb);
        }
    };

    issue(0); CP_COMMIT();
    issue(1); CP_COMMIT();

    #pragma unroll 1
    for (int c = 0; c < NC; c++) {
        if (c + 2 < NC) { issue(c + 2); CP_COMMIT(); CP_WAIT2(); }
        else if (c + 1 < NC) { CP_WAIT1(); }
        else { CP_WAIT0(); }
        __syncthreads();

        uint32_t st = sbase + (uint32_t)(c % 3) * STAGE;
        #pragma unroll
        for (int ks = 0; ks < 4; ks++) {
            uint32_t ah[4][4], bh[4][2];
            #pragma unroll
            for (int mi = 0; mi < 4; mi++) {
                uint32_t off = sw128((uint32_t)((arow + mi * 16) * 128 + (ks * 16 + akadd) * 2));
                ldsm4(ah[mi], st + A_OFF + off);
            }
            #pragma unroll
            for (int ng = 0; ng < 2; ng++) {
                uint32_t off = sw128((uint32_t)((nrow + ng * 16) * 128 + (ks * 16 + bkadd) * 2));
                uint32_t q[4];
                ldsm4(q, st + B_OFF + off);
                bh[2*ng][0] = q[0]; bh[2*ng][1] = q[1];
                bh[2*ng+1][0] = q[2]; bh[2*ng+1][1] = q[3];
            }
            #pragma unroll
            for (int mi = 0; mi < 4; mi++)
                #pragma unroll
                for (int ni = 0; ni < 4; ni++)
                    mma16816(acc[mi][ni], ah[mi], bh[ni]);
        }
        __syncthreads();
    }
}

#define ACC_INIT(acc) \
    _Pragma("unroll") for (int i = 0; i < 4; i++) \
    _Pragma("unroll") for (int j = 0; j < 4; j++) \
    _Pragma("unroll") for (int q = 0; q < 4; q++) acc[i][j][q] = 0.f;

// ---------------- GEMM1: combined = xhi @ whi^T + bias ----------------
__global__ __launch_bounds__(256, 2)
void gemm1_mma(const float* __restrict__ bias, float* __restrict__ Cout) {
    float acc[4][4][4];
    ACC_INIT(acc)
    const int m0 = blockIdx.y * BM, n0 = blockIdx.x * BN;
    mm_loop(acc, g_xhi, g_whi, HDIM, HDIM, m0, n0, 0, HDIM / BK);

    const int lane = threadIdx.x & 31, wid = threadIdx.x >> 5;
    const int wm = (wid >> 2) * 64, wn = (wid & 3) * 32;
    const int rbase = m0 + wm + (lane >> 2);
    const int cbase = n0 + wn + (lane & 3) * 2;
    #pragma unroll
    for (int mi = 0; mi < 4; mi++)
        #pragma unroll
        for (int ni = 0; ni < 4; ni++) {
            int r = rbase + mi * 16, cc = cbase + ni * 8;
            float2 bv = *(const float2*)(bias + cc);
            *(float2*)(Cout + (size_t)r * HDIM + cc) =
                make_float2(acc[mi][ni][0] + bv.x, acc[mi][ni][1] + bv.y);
            *(float2*)(Cout + (size_t)(r + 8) * HDIM + cc) =
                make_float2(acc[mi][ni][2] + bv.x, acc[mi][ni][3] + bv.y);
        }
}

// ---------------- GEMM2sym: P[s] += Xt[bi] @ Xt[bj]^T (lower triangle) ------
__global__ __launch_bounds__(256, 2)
void gemm2s_mma(int M) {
    float acc[4][4][4];
    ACC_INIT(acc)

    // triangular decode: blockIdx.x -> (bi, bj), bi >= bj
    int t = blockIdx.x;
    int bi = 0;
    while ((bi + 1) * (bi + 2) / 2 <= t) bi++;
    int bj = t - bi * (bi + 1) / 2;

    const int s = blockIdx.z;
    const int kper = M / KSPLIT;
    const int h0 = bi * BM, n0 = bj * BN;
    mm_loop(acc, g_xthi, g_xthi, M, M, h0, n0, s * kper, kper / BK);

    float* P = g_part + (size_t)s * HDIM * HDIM;
    const int lane = threadIdx.x & 31, wid = threadIdx.x >> 5;
    const int wm = (wid >> 2) * 64, wn = (wid & 3) * 32;
    const int rl = lane >> 2;
    const int cl = (lane & 3) * 2;

    #pragma unroll
    for (int mi = 0; mi < 4; mi++)
        #pragma unroll
        for (int ni = 0; ni < 4; ni++) {
            int r = h0 + wm + rl + mi * 16, cc = n0 + wn + cl + ni * 8;
            *(float2*)(P + (size_t)r * HDIM + cc) =
                make_float2(acc[mi][ni][0], acc[mi][ni][1]);
            *(float2*)(P + (size_t)(r + 8) * HDIM + cc) =
                make_float2(acc[mi][ni][2], acc[mi][ni][3]);
        }

    if (bi != bj) {
        extern __shared__ char dsm[];
        uint32_t raw = smem_u32(dsm);
        char* smp = dsm + (((raw + 1023) & ~1023u) - raw);
        float* tb = (float*)smp + (size_t)wid * (32 * 66);
        __syncthreads();   // mainloop smem fully consumed
        #pragma unroll
        for (int mi = 0; mi < 4; mi++)
            #pragma unroll
            for (int ni = 0; ni < 4; ni++) {
                int lr = rl + mi * 16;
                int lc = cl + ni * 8;
                tb[(lc + 0) * 66 + lr]     = acc[mi][ni][0];
                tb[(lc + 1) * 66 + lr]     = acc[mi][ni][1];
                tb[(lc + 0) * 66 + lr + 8] = acc[mi][ni][2];
                tb[(lc + 1) * 66 + lr + 8] = acc[mi][ni][3];
            }
        __syncwarp();
        const float* src = tb + lane * 66;
        float* dst = P + (size_t)(n0 + wn + lane) * HDIM + h0 + wm;
        #pragma unroll
        for (int j = 0; j < 16; j++) {
            float4 v;
            v.x = src[j * 4 + 0]; v.y = src[j * 4 + 1];
            v.z = src[j * 4 + 2]; v.w = src[j * 4 + 3];
            *(float4*)(dst + j * 4) = v;
        }
    }
}

// ---------------- GEMM3: neww = plastic + factor*(G@Wsum^T + s b^T);
// epilogue also emits sum-of-squares partials ----------------
__global__ __launch_bounds__(256, 2)
void gemm3_mma(const float* __restrict__ plastic,
               const float* __restrict__ rate, const float* __restrict__ hs,
               const float* __restrict__ bias,
               float* __restrict__ Wout, float invM) {
    __shared__ double shred[256];
    float acc[4][4][4];
    ACC_INIT(acc)
    const int m0 = blockIdx.y * BM, n0 = blockIdx.x * BN;
    mm_loop(acc, g_ghi, g_whi, HDIM, HDIM, m0, n0, 0, HDIM / BK);

    const float factor = rate[0] * hs[0] * invM;
    const int lane = threadIdx.x & 31, wid = threadIdx.x >> 5;
    const int wm = (wid >> 2) * 64, wn = (wid & 3) * 32;
    const int rbase = m0 + wm + (lane >> 2);
    const int cbase = n0 + wn + (lane & 3) * 2;
    double ss = 0.0;
    #pragma unroll
    for (int mi = 0; mi < 4; mi++)
        #pragma unroll
        for (int ni = 0; ni < 4; ni++) {
            int r = rbase + mi * 16, cc = cbase + ni * 8;
            float2 bv = *(const float2*)(bias + cc);
            float s0 = g_colsum[r], s1 = g_colsum[r + 8];
            float2 p0 = *(const float2*)(plastic + (size_t)r * HDIM + cc);
            float2 p1 = *(const float2*)(plastic + (size_t)(r + 8) * HDIM + cc);
            float v0 = p0.x + factor * (acc[mi][ni][0] + s0 * bv.x);
            float v1 = p0.y + factor * (acc[mi][ni][1] + s0 * bv.y);
            float v2 = p1.x + factor * (acc[mi][ni][2] + s1 * bv.x);
            float v3 = p1.y + factor * (acc[mi][ni][3] + s1 * bv.y);
            *(float2*)(Wout + (size_t)r * HDIM + cc)       = make_float2(v0, v1);
            *(float2*)(Wout + (size_t)(r + 8) * HDIM + cc) = make_float2(v2, v3);
            ss += (double)v0 * v0 + (double)v1 * v1
                + (double)v2 * v2 + (double)v3 * v3;
        }
    shred[threadIdx.x] = ss;
    __syncthreads();
    for (int off = 128; off > 0; off >>= 1) {
        if (threadIdx.x < off) shred[threadIdx.x] += shred[threadIdx.x + off];
        __syncthreads();
    }
    if (threadIdx.x == 0)
        g_partials[blockIdx.y * NTILE + blockIdx.x] = shred[0];
}

// ---------------- norm finalize + scale ----------------
__global__ void finalize_kernel() {
    __shared__ double sh[256];
    const int tid = threadIdx.x;
    double s = (tid < NRED) ? g_partials[tid] : 0.0;
    sh[tid] = s;
    __syncthreads();
    for (int off = 128; off > 0; off >>= 1) {
        if (tid < off) sh[tid] += sh[tid + off];
        __syncthreads();
    }
    if (tid == 0) {
        double norm = sqrt(sh[0]);
        g_scale = (norm > 1.0) ? (float)(1.0 / norm) : 1.0f;
    }
}

__global__ void scale_kernel(float* __restrict__ W) {
    size_t i = (size_t)blockIdx.x * blockDim.x + threadIdx.x;
    const float s = g_scale;
    float4 v = ((float4*)W)[i];
    v.x *= s; v.y *= s; v.z *= s; v.w *= s;
    ((float4*)W)[i] = v;
}

// ---------------- launch (two-stream fork/join, graph-capturable) -----------
extern "C" void kernel_launch(void* const* d_in, const int* in_sizes, int n_in,
                              void* d_out, int out_size) {
    const float* x    = (const float*)d_in[0];  // [M, H]
    const float* pw   = (const float*)d_in[1];  // [H, H]
    const float* rate = (const float*)d_in[2];  // [1]
    const float* fw   = (const float*)d_in[3];  // [H, H]
    const float* fb   = (const float*)d_in[4];  // [H]
    const float* hs   = (const float*)d_in[5];  // scalar

    const int M = in_sizes[0] / HDIM;           // 16384
    float* combined = (float*)d_out;
    float* neww     = (float*)d_out + (size_t)M * HDIM;

    static bool init_done = false;
    static cudaStream_t s2;
    static cudaEvent_t evFork, evJoin;
    if (!init_done) {
        cudaFuncSetAttribute(gemm1_mma,  cudaFuncAttributeMaxDynamicSharedMemorySize, SMEM_DYN);
        cudaFuncSetAttribute(gemm2s_mma, cudaFuncAttributeMaxDynamicSharedMemorySize, SMEM_DYN);
        cudaFuncSetAttribute(gemm3_mma,  cudaFuncAttributeMaxDynamicSharedMemorySize, SMEM_DYN);
        cudaStreamCreateWithFlags(&s2, cudaStreamNonBlocking);
        cudaEventCreateWithFlags(&evFork, cudaEventDisableTiming);
        cudaEventCreateWithFlags(&evJoin, cudaEventDisableTiming);
        init_done = true;
    }

    __half *xhi, *xthi, *whi, *ghi;
    float* cs;
    cudaGetSymbolAddress((void**)&xhi,  g_xhi);
    cudaGetSymbolAddress((void**)&xthi, g_xthi);
    cudaGetSymbolAddress((void**)&whi,  g_whi);
    cudaGetSymbolAddress((void**)&ghi,  g_ghi);
    cudaGetSymbolAddress((void**)&cs,   g_colsum);

    // prep on the captured (default) stream
    wsum_hi_kernel<<<HDIM * HDIM / 4 / 256, 256>>>(fw, pw, whi);
    {
        dim3 g(HDIM / 32, M / 32);
        xprep_kernel<<<g, 256>>>(x, xhi, xthi, M, HDIM);
    }

    // fork: side stream computes the whole new_w chain
    cudaEventRecord(evFork, 0);
    cudaStreamWaitEvent(s2, evFork, 0);

    colsum_kernel<<<HDIM, 256, 0, s2>>>(xthi, cs, M);
    {
        dim3 g(NTRI, 1, KSPLIT);
        gemm2s_mma<<<g, 256, SMEM_DYN, s2>>>(M);
    }
    gsum_hi_kernel<<<HDIM * HDIM / 4 / 256, 256, 0, s2>>>(ghi);
    {
        dim3 g(NTILE, NTILE);
        gemm3_mma<<<g, 256, SMEM_DYN, s2>>>(pw, rate, hs, fb, neww, 1.0f / (float)M);
    }
    finalize_kernel<<<1, 256, 0, s2>>>();
    scale_kernel<<<HDIM * HDIM / 4 / 256, 256, 0, s2>>>(neww);

    // main stream: GEMM1 (combined) runs concurrently with the s2 chain
    {
        dim3 g(HDIM / BN, M / BM);
        gemm1_mma<<<g, 256, SMEM_DYN>>>(fb, combined);
    }

    // join
    cudaEventRecord(evJoin, s2);
    cudaStreamWaitEvent(0, evJoin, 0);
}